// round 7
// baseline (speedup 1.0000x reference)
#include <cuda_runtime.h>

#define BB  4
#define CC  256
#define CQK 32
#define NN  4096
#define MT  32               // m-tile per step
#define STEPS (NN / MT)      // 128
#define LOG2E 1.4426950408889634f

// q/k: [b][n][c-perm] (perm in 8-groups [k0,k4,k1,k5,k2,k6,k3,k7]), tf32.
// q pre-scaled by log2(e).  v: [b][c][m-perm], tf32.
__device__ float g_qt[BB * NN * CQK];
__device__ float g_kt[BB * NN * CQK];
__device__ float g_v [BB * CC * NN];

// smem layout (floats)
#define OFF_Q  0                 // 128 x 40
#define OFF_K  5120              // 2 x 32 x 40
#define OFF_V  7680              // 3 x 256 x 40
#define OFF_P  38400             // 8 warps x 32 x 40 (warp-private copies)
#define SMEM_FLOATS 48640        // 194560 bytes
// epilogue transpose buffer reuses OFF_V (needs 128*132 = 16896 <= 30720)

// ===========================================================================
__device__ __forceinline__ unsigned smem_u32(const void* p) {
    unsigned a;
    asm("{ .reg .u64 t; cvta.to.shared.u64 t, %1; cvt.u32.u64 %0, t; }"
        : "=r"(a) : "l"(p));
    return a;
}
__device__ __forceinline__ float to_tf32(float x) {
    unsigned u;
    asm("cvt.rna.tf32.f32 %0, %1;" : "=r"(u) : "f"(x));
    return __uint_as_float(u);
}
__device__ __forceinline__ float ex2(float x) {
    float y;
    asm("ex2.approx.ftz.f32 %0, %1;" : "=f"(y) : "f"(x));
    return y;
}
__device__ __forceinline__ void cp16(unsigned dst, const void* src) {
    asm volatile("cp.async.cg.shared.global [%0], [%1], 16;" :: "r"(dst), "l"(src));
}
#define CP_COMMIT()  asm volatile("cp.async.commit_group;")
#define CP_WAIT(n)   asm volatile("cp.async.wait_group %0;" :: "n"(n))

__device__ __forceinline__ void lds2(unsigned addr, unsigned& x, unsigned& y) {
    asm volatile("ld.shared.v2.b32 {%0, %1}, [%2];" : "=r"(x), "=r"(y) : "r"(addr));
}
__device__ __forceinline__ void mma8(float c[4],
                                     unsigned a0, unsigned a1, unsigned a2, unsigned a3,
                                     unsigned b0, unsigned b1) {
    asm volatile(
        "mma.sync.aligned.m16n8k8.row.col.f32.tf32.tf32.f32 "
        "{%0,%1,%2,%3}, {%4,%5,%6,%7}, {%8,%9}, {%0,%1,%2,%3};"
        : "+f"(c[0]), "+f"(c[1]), "+f"(c[2]), "+f"(c[3])
        : "r"(a0), "r"(a1), "r"(a2), "r"(a3), "r"(b0), "r"(b1));
}

// ===========================================================================
// 1a) Fused q+k projection: grid (NN/256, 4, BB), block 256.
//     by: 0..1 -> q o-tiles, 2..3 -> k o-tiles. Thread: 16 o x 1 n.
// ===========================================================================
__global__ void qk_proj_kernel(const float* __restrict__ x,
                               const float* __restrict__ Wq,
                               const float* __restrict__ bq,
                               const float* __restrict__ Wk,
                               const float* __restrict__ bk) {
    __shared__ float sW[CC][16];
    __shared__ float sb[16];

    const int b     = blockIdx.z;
    const int which = blockIdx.y >> 1;          // 0=q, 1=k
    const int o0    = (blockIdx.y & 1) * 16;
    const int tid   = threadIdx.x;

    const float* W    = which ? Wk : Wq;
    const float* bias = which ? bk : bq;
    const float  sc   = which ? 1.0f : LOG2E;
    float*       yt   = which ? g_kt : g_qt;

#pragma unroll
    for (int i = 0; i < 16; i++) {
        int idx = tid + i * 256;
        int o = idx >> 8, c = idx & 255;
        sW[c][o] = W[(o0 + o) * CC + c];
    }
    if (tid < 16) sb[tid] = bias[o0 + tid];
    __syncthreads();

    const int n = blockIdx.x * 256 + tid;
    const float* xp = x + (size_t)b * CC * NN + n;

    float acc[16];
#pragma unroll
    for (int o = 0; o < 16; o++) acc[o] = 0.f;

#pragma unroll 4
    for (int c = 0; c < CC; c++) {
        float xv = xp[(size_t)c * NN];
        float4 w0 = *(const float4*)&sW[c][0];
        float4 w1 = *(const float4*)&sW[c][4];
        float4 w2 = *(const float4*)&sW[c][8];
        float4 w3 = *(const float4*)&sW[c][12];
        acc[0]  = fmaf(w0.x, xv, acc[0]);  acc[1]  = fmaf(w0.y, xv, acc[1]);
        acc[2]  = fmaf(w0.z, xv, acc[2]);  acc[3]  = fmaf(w0.w, xv, acc[3]);
        acc[4]  = fmaf(w1.x, xv, acc[4]);  acc[5]  = fmaf(w1.y, xv, acc[5]);
        acc[6]  = fmaf(w1.z, xv, acc[6]);  acc[7]  = fmaf(w1.w, xv, acc[7]);
        acc[8]  = fmaf(w2.x, xv, acc[8]);  acc[9]  = fmaf(w2.y, xv, acc[9]);
        acc[10] = fmaf(w2.z, xv, acc[10]); acc[11] = fmaf(w2.w, xv, acc[11]);
        acc[12] = fmaf(w3.x, xv, acc[12]); acc[13] = fmaf(w3.y, xv, acc[13]);
        acc[14] = fmaf(w3.z, xv, acc[14]); acc[15] = fmaf(w3.w, xv, acc[15]);
    }

    float vv[16];
#pragma unroll
    for (int o = 0; o < 16; o++) vv[o] = to_tf32((acc[o] + sb[o]) * sc);
    float* bp = yt + ((size_t)b * NN + n) * CQK + o0;
    *(float4*)(bp + 0)  = make_float4(vv[0],  vv[4],  vv[1],  vv[5]);
    *(float4*)(bp + 4)  = make_float4(vv[2],  vv[6],  vv[3],  vv[7]);
    *(float4*)(bp + 8)  = make_float4(vv[8],  vv[12], vv[9],  vv[13]);
    *(float4*)(bp + 12) = make_float4(vv[10], vv[14], vv[11], vv[15]);
}

// ===========================================================================
// 1b) V projection: [c][m] layout, m-permuted, tf32. grid (4, 16, BB), 256 thr.
// ===========================================================================
__global__ void v_proj_kernel(const float* __restrict__ x,
                              const float* __restrict__ W,
                              const float* __restrict__ bias) {
    __shared__ float sW[CC][16];
    __shared__ float sb[16];

    const int b   = blockIdx.z;
    const int o0  = blockIdx.y * 16;
    const int tid = threadIdx.x;

#pragma unroll
    for (int i = 0; i < 16; i++) {
        int idx = tid + i * 256;
        int o = idx >> 8, c = idx & 255;
        sW[c][o] = W[(o0 + o) * CC + c];
    }
    if (tid < 16) sb[tid] = bias[o0 + tid];
    __syncthreads();

    const int n0 = blockIdx.x * 1024 + tid * 4;
    float acc[16][4];
#pragma unroll
    for (int o = 0; o < 16; o++)
#pragma unroll
        for (int j = 0; j < 4; j++) acc[o][j] = 0.f;

    const float* xp = x + (size_t)b * CC * NN + n0;

#pragma unroll 4
    for (int c = 0; c < CC; c++) {
        float4 xv = *(const float4*)(xp + (size_t)c * NN);
        float4 w0 = *(const float4*)&sW[c][0];
        float4 w1 = *(const float4*)&sW[c][4];
        float4 w2 = *(const float4*)&sW[c][8];
        float4 w3 = *(const float4*)&sW[c][12];
        float wv[16] = {w0.x, w0.y, w0.z, w0.w, w1.x, w1.y, w1.z, w1.w,
                        w2.x, w2.y, w2.z, w2.w, w3.x, w3.y, w3.z, w3.w};
#pragma unroll
        for (int o = 0; o < 16; o++) {
            acc[o][0] = fmaf(wv[o], xv.x, acc[o][0]);
            acc[o][1] = fmaf(wv[o], xv.y, acc[o][1]);
            acc[o][2] = fmaf(wv[o], xv.z, acc[o][2]);
            acc[o][3] = fmaf(wv[o], xv.w, acc[o][3]);
        }
    }

    float* yp = g_v + ((size_t)b * CC + o0) * NN + n0;
    const bool ev = (tid & 1) == 0;
#pragma unroll
    for (int o = 0; o < 16; o++) {
        float v0 = to_tf32(acc[o][0] + sb[o]);
        float v1 = to_tf32(acc[o][1] + sb[o]);
        float v2 = to_tf32(acc[o][2] + sb[o]);
        float v3 = to_tf32(acc[o][3] + sb[o]);
        float t1 = __shfl_xor_sync(0xffffffffu, ev ? v2 : v0, 1);
        float t2 = __shfl_xor_sync(0xffffffffu, ev ? v3 : v1, 1);
        float4 r = ev ? make_float4(v0, t1, v1, t2)
                      : make_float4(t1, v2, t2, v3);
        *(float4*)(yp + (size_t)o * NN) = r;
    }
}

// ===========================================================================
// 2) Flash attention, deferred-MMA pipeline.
//    Warp tile: 32 n-rows (wr=wid>>1) x 128 c (wc=wid&1); scores duplicated
//    per warp pair so softmax/P are warp-private. Per step s:
//      scores(s) -> out-MMA(s-1) -> softmax(s)+P-store (syncwarp only).
//    One __syncthreads per step (K 2-buf, V 3-buf rotation).
// ===========================================================================
__global__ __launch_bounds__(256, 1) void flash_kernel(const float* __restrict__ x,
                                                       float* __restrict__ out) {
    extern __shared__ float sm[];

    const int b   = blockIdx.y;
    const int n0  = blockIdx.x * 128;
    const int tid = threadIdx.x;
    const int wid = tid >> 5, lane = tid & 31;
    const int r4 = lane >> 2, q = lane & 3;
    const int wr = wid >> 1, wc = wid & 1;

    const unsigned sb4 = smem_u32(sm);
    const unsigned sQ  = sb4 + OFF_Q * 4;
    const unsigned sK  = sb4 + OFF_K * 4;
    const unsigned sV  = sb4 + OFF_V * 4;
    const unsigned sPw = sb4 + (OFF_P + wid * MT * 40) * 4;   // warp-private P
    float* fPw = sm + OFF_P + wid * MT * 40;

    const float* qg  = g_qt + ((size_t)b * NN + n0) * CQK;
    const float* kg0 = g_kt + (size_t)b * NN * CQK;
    const float* vg0 = g_v  + (size_t)b * CC * NN;

    // ---- prefetch lambda: K(s) 32x32, V(s) 256x32 (both stride 40)
    auto issue = [&](int s) {
        const unsigned kd = sK + (unsigned)(s & 1) * (MT * 40 * 4);
        {
            int row = tid >> 3, p = tid & 7;
            cp16(kd + (unsigned)(row * 40 + p * 4) * 4,
                 kg0 + (size_t)(s * MT + row) * CQK + p * 4);
        }
        const unsigned vd = sV + (unsigned)(s % 3) * (256 * 40 * 4);
#pragma unroll
        for (int i = 0; i < 8; i++) {
            int idx = tid + i * 256;
            int row = idx >> 3, p = idx & 7;
            cp16(vd + (unsigned)(row * 40 + p * 4) * 4,
                 vg0 + (size_t)row * NN + s * MT + p * 4);
        }
        CP_COMMIT();
    };

    // ---- prologue: Q + K(0) + V(0)
#pragma unroll
    for (int i = 0; i < 4; i++) {
        int idx = tid + i * 256;
        int row = idx >> 3, p = idx & 7;
        cp16(sQ + (unsigned)(row * 40 + p * 4) * 4, qg + (size_t)row * CQK + p * 4);
    }
    issue(0);
    CP_WAIT(0);
    __syncthreads();

    // q fragments: warp rows wr*32 .. +31
    unsigned qf[2][4][4];
#pragma unroll
    for (int mt = 0; mt < 2; mt++)
#pragma unroll
        for (int kk = 0; kk < 4; kk++) {
            unsigned ad = sQ + (unsigned)((wr * 32 + mt * 16 + r4) * 40 + kk * 8 + 2 * q) * 4;
            lds2(ad,              qf[mt][kk][0], qf[mt][kk][2]);
            lds2(ad + 8 * 40 * 4, qf[mt][kk][1], qf[mt][kk][3]);
        }

    float acc[2][16][4];
#pragma unroll
    for (int mt = 0; mt < 2; mt++)
#pragma unroll
        for (int nt = 0; nt < 16; nt++)
#pragma unroll
            for (int j = 0; j < 4; j++) acc[mt][nt][j] = 0.f;

    float mA[2] = {-1e30f, -1e30f}, mB[2] = {-1e30f, -1e30f};
    float lA[2] = {0.f, 0.f},       lB[2] = {0.f, 0.f};
    float scPA[2] = {1.f, 1.f},     scPB[2] = {1.f, 1.f};

    for (int s = 0; s < STEPS; s++) {
        if (s > 0) { CP_WAIT(0); __syncthreads(); }
        if (s + 1 < STEPS) issue(s + 1);

        // ---- scores(s): 32 rows x 32 m per warp (duplicated across pair)
        const unsigned kbuf = sK + (unsigned)(s & 1) * (MT * 40 * 4);
        float sacc[2][4][4];
#pragma unroll
        for (int mt = 0; mt < 2; mt++)
#pragma unroll
            for (int nt = 0; nt < 4; nt++)
#pragma unroll
                for (int j = 0; j < 4; j++) sacc[mt][nt][j] = 0.f;

#pragma unroll
        for (int kk = 0; kk < 4; kk++) {
            unsigned kb[4][2];
#pragma unroll
            for (int nt = 0; nt < 4; nt++)
                lds2(kbuf + (unsigned)((nt * 8 + r4) * 40 + kk * 8 + 2 * q) * 4,
                     kb[nt][0], kb[nt][1]);
#pragma unroll
            for (int mt = 0; mt < 2; mt++)
#pragma unroll
                for (int nt = 0; nt < 4; nt++)
                    mma8(sacc[mt][nt], qf[mt][kk][0], qf[mt][kk][1],
                         qf[mt][kk][2], qf[mt][kk][3], kb[nt][0], kb[nt][1]);
        }

        // ---- out-MMA(s-1): acc += P(s-1) @ V(s-1)^T  (deferred)
        if (s > 0) {
            bool ones = (scPA[0] == 1.f) && (scPA[1] == 1.f) &&
                        (scPB[0] == 1.f) && (scPB[1] == 1.f);
            if (!__all_sync(0xffffffffu, ones)) {
#pragma unroll
                for (int mt = 0; mt < 2; mt++)
#pragma unroll
                    for (int nt = 0; nt < 16; nt++) {
                        acc[mt][nt][0] *= scPA[mt];
                        acc[mt][nt][1] *= scPA[mt];
                        acc[mt][nt][2] *= scPB[mt];
                        acc[mt][nt][3] *= scPB[mt];
                    }
            }
            const unsigned vbuf = sV + (unsigned)((s - 1) % 3) * (256 * 40 * 4);
#pragma unroll
            for (int kk = 0; kk < 4; kk++) {
                unsigned af[2][4];
#pragma unroll
                for (int mt = 0; mt < 2; mt++) {
                    unsigned ad = sPw + (unsigned)((mt * 16 + r4) * 40 + kk * 8 + 2 * q) * 4;
                    lds2(ad,              af[mt][0], af[mt][2]);
                    lds2(ad + 8 * 40 * 4, af[mt][1], af[mt][3]);
                }
#pragma unroll
                for (int ntg = 0; ntg < 2; ntg++) {
                    unsigned bf[8][2];
#pragma unroll
                    for (int j = 0; j < 8; j++) {
                        int nt = ntg * 8 + j;
                        lds2(vbuf + (unsigned)((wc * 128 + nt * 8 + r4) * 40 + kk * 8 + 2 * q) * 4,
                             bf[j][0], bf[j][1]);
                    }
#pragma unroll
                    for (int mt = 0; mt < 2; mt++)
#pragma unroll
                        for (int j = 0; j < 8; j++)
                            mma8(acc[mt][ntg * 8 + j], af[mt][0], af[mt][1],
                                 af[mt][2], af[mt][3], bf[j][0], bf[j][1]);
                }
            }
        }

        // ---- softmax(s), warp-local; P(s) -> warp-private smem
#pragma unroll
        for (int mt = 0; mt < 2; mt++) {
            float rmA = -1e30f, rmB = -1e30f;
#pragma unroll
            for (int nt = 0; nt < 4; nt++) {
                rmA = fmaxf(rmA, fmaxf(sacc[mt][nt][0], sacc[mt][nt][1]));
                rmB = fmaxf(rmB, fmaxf(sacc[mt][nt][2], sacc[mt][nt][3]));
            }
#pragma unroll
            for (int off = 1; off <= 2; off <<= 1) {
                rmA = fmaxf(rmA, __shfl_xor_sync(0xffffffffu, rmA, off));
                rmB = fmaxf(rmB, __shfl_xor_sync(0xffffffffu, rmB, off));
            }
            const float mnA = fmaxf(mA[mt], rmA), mnB = fmaxf(mB[mt], rmB);
            const float scA = ex2(mA[mt] - mnA),  scB = ex2(mB[mt] - mnB);
            mA[mt] = mnA; mB[mt] = mnB;

            float lsA = 0.f, lsB = 0.f;
#pragma unroll
            for (int nt = 0; nt < 4; nt++) {
                float p0 = to_tf32(ex2(sacc[mt][nt][0] - mnA));
                float p1 = to_tf32(ex2(sacc[mt][nt][1] - mnA));
                float p2 = to_tf32(ex2(sacc[mt][nt][2] - mnB));
                float p3 = to_tf32(ex2(sacc[mt][nt][3] - mnB));
                sacc[mt][nt][0] = p0; sacc[mt][nt][1] = p1;
                sacc[mt][nt][2] = p2; sacc[mt][nt][3] = p3;
                lsA += p0 + p1; lsB += p2 + p3;
            }
#pragma unroll
            for (int off = 1; off <= 2; off <<= 1) {
                lsA += __shfl_xor_sync(0xffffffffu, lsA, off);
                lsB += __shfl_xor_sync(0xffffffffu, lsB, off);
            }
            lA[mt] = lA[mt] * scA + lsA;
            lB[mt] = lB[mt] * scB + lsB;
            scPA[mt] = scA; scPB[mt] = scB;

#pragma unroll
            for (int nt = 0; nt < 4; nt++)
#pragma unroll
                for (int j = 0; j < 4; j++) {
                    int k = 2 * q + (j & 1);
                    int pos = 2 * (k & 3) + (k >> 2);
                    fPw[(mt * 16 + r4 + 8 * (j >> 1)) * 40 + nt * 8 + pos] = sacc[mt][nt][j];
                }
        }
        __syncwarp();
    }

    // ---- final out-MMA(STEPS-1)
    {
        bool ones = (scPA[0] == 1.f) && (scPA[1] == 1.f) &&
                    (scPB[0] == 1.f) && (scPB[1] == 1.f);
        if (!__all_sync(0xffffffffu, ones)) {
#pragma unroll
            for (int mt = 0; mt < 2; mt++)
#pragma unroll
                for (int nt = 0; nt < 16; nt++) {
                    acc[mt][nt][0] *= scPA[mt];
                    acc[mt][nt][1] *= scPA[mt];
                    acc[mt][nt][2] *= scPB[mt];
                    acc[mt][nt][3] *= scPB[mt];
                }
        }
        const unsigned vbuf = sV + (unsigned)((STEPS - 1) % 3) * (256 * 40 * 4);
#pragma unroll
        for (int kk = 0; kk < 4; kk++) {
            unsigned af[2][4];
#pragma unroll
            for (int mt = 0; mt < 2; mt++) {
                unsigned ad = sPw + (unsigned)((mt * 16 + r4) * 40 + kk * 8 + 2 * q) * 4;
                lds2(ad,              af[mt][0], af[mt][2]);
                lds2(ad + 8 * 40 * 4, af[mt][1], af[mt][3]);
            }
#pragma unroll
            for (int ntg = 0; ntg < 2; ntg++) {
                unsigned bf[8][2];
#pragma unroll
                for (int j = 0; j < 8; j++) {
                    int nt = ntg * 8 + j;
                    lds2(vbuf + (unsigned)((wc * 128 + nt * 8 + r4) * 40 + kk * 8 + 2 * q) * 4,
                         bf[j][0], bf[j][1]);
                }
#pragma unroll
                for (int mt = 0; mt < 2; mt++)
#pragma unroll
                    for (int j = 0; j < 8; j++)
                        mma8(acc[mt][ntg * 8 + j], af[mt][0], af[mt][1],
                             af[mt][2], af[mt][3], bf[j][0], bf[j][1]);
            }
        }
    }

    // ---- normalize by l (all warp-local)
    float linvA[2], linvB[2];
#pragma unroll
    for (int mt = 0; mt < 2; mt++) { linvA[mt] = 1.f / lA[mt]; linvB[mt] = 1.f / lB[mt]; }
#pragma unroll
    for (int mt = 0; mt < 2; mt++)
#pragma unroll
        for (int nt = 0; nt < 16; nt++) {
            acc[mt][nt][0] *= linvA[mt];
            acc[mt][nt][1] *= linvA[mt];
            acc[mt][nt][2] *= linvB[mt];
            acc[mt][nt][3] *= linvB[mt];
        }

    // ---- epilogue: transpose n x c -> c x n via smem (reuse V), +x, store
    float* fT = sm + OFF_V;   // 128 x 132
    const float* xb = x   + (size_t)b * CC * NN + n0;
    float*       ob = out + (size_t)b * CC * NN + n0;
#pragma unroll 1
    for (int ch = 0; ch < 2; ch++) {
        __syncthreads();
        if (wc == ch) {
#pragma unroll
            for (int mt = 0; mt < 2; mt++)
#pragma unroll
                for (int nt = 0; nt < 16; nt++)
#pragma unroll
                    for (int j = 0; j < 4; j++) {
                        int cl = nt * 8 + 2 * q + (j & 1);
                        int rn = wr * 32 + mt * 16 + r4 + 8 * (j >> 1);
                        fT[cl * 132 + rn] = acc[mt][nt][j];
                    }
        }
        __syncthreads();
#pragma unroll
        for (int i = 0; i < 16; i++) {
            int idx = tid + i * 256;
            int cr = idx >> 5;
            int n4 = (idx & 31) * 4;
            float4 t = *(const float4*)&fT[cr * 132 + n4];
            const size_t go = (size_t)(ch * 128 + cr) * NN + n4;
            float4 xv = *(const float4*)(xb + go);
            *(float4*)(ob + go) = make_float4(t.x + xv.x, t.y + xv.y,
                                              t.z + xv.z, t.w + xv.w);
        }
    }
}

// ===========================================================================
extern "C" void kernel_launch(void* const* d_in, const int* in_sizes, int n_in,
                              void* d_out, int out_size) {
    const float* x  = (const float*)d_in[0];
    const float* Wq = (const float*)d_in[1];
    const float* bq = (const float*)d_in[2];
    const float* Wk = (const float*)d_in[3];
    const float* bk = (const float*)d_in[4];
    const float* Wv = (const float*)d_in[5];
    const float* bv = (const float*)d_in[6];
    float* out = (float*)d_out;

    qk_proj_kernel<<<dim3(NN / 256, 4, BB), 256>>>(x, Wq, bq, Wk, bk);
    v_proj_kernel<<<dim3(NN / 1024, CC / 16, BB), 256>>>(x, Wv, bv);

    const int dyn = SMEM_FLOATS * 4;   // 194560 B
    cudaFuncSetAttribute(flash_kernel,
                         cudaFuncAttributeMaxDynamicSharedMemorySize, dyn);
    flash_kernel<<<dim3(NN / 128, BB), 256, dyn>>>(x, out);
}

// round 8
// speedup vs baseline: 1.3454x; 1.3454x over previous
#include <cuda_runtime.h>

#define BB  4
#define CC  256
#define CQK 32
#define NN  4096
#define LOG2E 1.4426950408889634f

// q/k: [b][n][c-perm] (perm in 8-groups [k0,k4,k1,k5,k2,k6,k3,k7]), tf32.
// v: [b][c][m-perm], tf32.  (LOG2E applied to q inside flash kernel.)
__device__ float g_qt[BB * NN * CQK];
__device__ float g_kt[BB * NN * CQK];
__device__ float g_v [BB * CC * NN];

// ---- flash smem layout (floats) — R6 constants
#define OFF_Q  0            // 128 x 40
#define OFF_K  5120         // 2 x 64 x 40
#define OFF_V  10240        // 2 x 256 x 72
#define OFF_P  47104        // 128 x 72
#define OFF_SC 56320        // 128
#define OFF_L  56448        // 128
#define SMEM_FLOATS 56576   // 226304 bytes

// ---- proj smem layout (floats)
#define P_OFF_SX 0          // 2 x 128 x 36
#define P_OFF_SW 9216       // 2 x 320 x 36
#define P_OFF_SB 32256      // 320
#define P_SMEM_FLOATS 32576 // 130304 bytes (epilogue 80x132 reuses P_OFF_SW)

// ===========================================================================
__device__ __forceinline__ unsigned smem_u32(const void* p) {
    unsigned a;
    asm("{ .reg .u64 t; cvta.to.shared.u64 t, %1; cvt.u32.u64 %0, t; }"
        : "=r"(a) : "l"(p));
    return a;
}
__device__ __forceinline__ float to_tf32(float x) {
    unsigned u;
    asm("cvt.rna.tf32.f32 %0, %1;" : "=r"(u) : "f"(x));
    return __uint_as_float(u);
}
__device__ __forceinline__ float ex2(float x) {
    float y;
    asm("ex2.approx.ftz.f32 %0, %1;" : "=f"(y) : "f"(x));
    return y;
}
__device__ __forceinline__ void cp16(unsigned dst, const void* src) {
    asm volatile("cp.async.cg.shared.global [%0], [%1], 16;" :: "r"(dst), "l"(src));
}
__device__ __forceinline__ void cp4(unsigned dst, const void* src) {
    asm volatile("cp.async.ca.shared.global [%0], [%1], 4;" :: "r"(dst), "l"(src));
}
#define CP_COMMIT()  asm volatile("cp.async.commit_group;")
#define CP_WAIT(n)   asm volatile("cp.async.wait_group %0;" :: "n"(n))

__device__ __forceinline__ void lds2(unsigned addr, unsigned& x, unsigned& y) {
    asm volatile("ld.shared.v2.b32 {%0, %1}, [%2];" : "=r"(x), "=r"(y) : "r"(addr));
}
__device__ __forceinline__ unsigned lds1(unsigned addr) {
    unsigned v;
    asm volatile("ld.shared.b32 %0, [%1];" : "=r"(v) : "r"(addr));
    return v;
}
__device__ __forceinline__ void mma8(float c[4],
                                     unsigned a0, unsigned a1, unsigned a2, unsigned a3,
                                     unsigned b0, unsigned b1) {
    asm volatile(
        "mma.sync.aligned.m16n8k8.row.col.f32.tf32.tf32.f32 "
        "{%0,%1,%2,%3}, {%4,%5,%6,%7}, {%8,%9}, {%0,%1,%2,%3};"
        : "+f"(c[0]), "+f"(c[1]), "+f"(c[2]), "+f"(c[3])
        : "r"(a0), "r"(a1), "r"(a2), "r"(a3), "r"(b0), "r"(b1));
}

// ===========================================================================
// 1) Fused q+k+v projection via tensor cores.
//    GEMM: D[320 o][128 n] = Wcat[320][256] @ x[256][n-tile], K chunked by 32,
//    double-buffered cp.async (x transposed via 4B cp.async).
//    Warp grid 4(M=80) x 2(N=64). grid (NN/128, BB), 256 threads.
// ===========================================================================
__global__ __launch_bounds__(256, 1) void proj_fused_kernel(
        const float* __restrict__ x,
        const float* __restrict__ Wq, const float* __restrict__ bq,
        const float* __restrict__ Wk, const float* __restrict__ bk,
        const float* __restrict__ Wv, const float* __restrict__ bv) {
    extern __shared__ float psm[];

    const int b   = blockIdx.y;
    const int n0  = blockIdx.x * 128;
    const int tid = threadIdx.x;
    const int wid = tid >> 5, lane = tid & 31;
    const int r4 = lane >> 2, q = lane & 3;
    const int wm = wid >> 1, wn = wid & 1;

    const unsigned sb4 = smem_u32(psm);
    const unsigned sX  = sb4 + P_OFF_SX * 4;
    const unsigned sW  = sb4 + P_OFF_SW * 4;
    float* fB = psm + P_OFF_SB;

    // biases -> smem: [0..31]=bq, [32..63]=bk, [64..319]=bv
    {
        int i = tid;
        if (i < 32) fB[i] = bq[i];
        else if (i < 64) fB[i] = bk[i - 32];
        else fB[i] = bv[i - 64];
        i = tid + 256;
        if (i < 320) fB[i] = bv[i - 64];
    }

    auto issue = [&](int ch) {
        const int buf = ch & 1;
        // W chunk: 320 rows x 32 c, natural k order
        const unsigned wd = sW + (unsigned)buf * (320 * 36 * 4);
#pragma unroll
        for (int i = 0; i < 10; i++) {
            int idx = tid + i * 256;
            int row = idx >> 3, seg = idx & 7;
            int c = ch * 32 + seg * 4;
            const float* src = (row < 32) ? (Wq + row * 256 + c)
                             : (row < 64) ? (Wk + (row - 32) * 256 + c)
                                          : (Wv + (row - 64) * 256 + c);
            cp16(wd + (unsigned)(row * 36 + seg * 4) * 4, src);
        }
        // x chunk transposed: smem [n][c], 4B cp.async
        const unsigned xd = sX + (unsigned)buf * (128 * 36 * 4);
#pragma unroll
        for (int i = 0; i < 16; i++) {
            int idx = tid + i * 256;
            int c = idx >> 7, n = idx & 127;
            cp4(xd + (unsigned)(n * 36 + c) * 4,
                x + ((size_t)b * CC + ch * 32 + c) * NN + n0 + n);
        }
        CP_COMMIT();
    };

    float acc[5][8][4];
#pragma unroll
    for (int mt = 0; mt < 5; mt++)
#pragma unroll
        for (int nt = 0; nt < 8; nt++)
#pragma unroll
            for (int j = 0; j < 4; j++) acc[mt][nt][j] = 0.f;

    issue(0);
    for (int ch = 0; ch < 8; ch++) {
        if (ch < 7) { issue(ch + 1); CP_WAIT(1); }
        else        { CP_WAIT(0); }
        __syncthreads();

        const int buf = ch & 1;
        const unsigned swb = sW + (unsigned)buf * (320 * 36 * 4);
        const unsigned sxb = sX + (unsigned)buf * (128 * 36 * 4);
#pragma unroll
        for (int kk = 0; kk < 4; kk++) {
            unsigned a[5][4];
#pragma unroll
            for (int mt = 0; mt < 5; mt++) {
                unsigned base = swb + (unsigned)((wm * 80 + mt * 16 + r4) * 36 + kk * 8 + q) * 4;
                a[mt][0] = lds1(base);
                a[mt][1] = lds1(base + 8 * 36 * 4);
                a[mt][2] = lds1(base + 16);
                a[mt][3] = lds1(base + 8 * 36 * 4 + 16);
            }
            unsigned bb[8][2];
#pragma unroll
            for (int nt = 0; nt < 8; nt++) {
                unsigned nb = sxb + (unsigned)((wn * 64 + nt * 8 + r4) * 36 + kk * 8 + q) * 4;
                bb[nt][0] = lds1(nb);
                bb[nt][1] = lds1(nb + 16);
            }
#pragma unroll
            for (int mt = 0; mt < 5; mt++)
#pragma unroll
                for (int nt = 0; nt < 8; nt++)
                    mma8(acc[mt][nt], a[mt][0], a[mt][1], a[mt][2], a[mt][3],
                         bb[nt][0], bb[nt][1]);
        }
        __syncthreads();
    }

    // ---- epilogue: stage 80-row chunks via smem, write permuted layouts
    float* fE = psm + P_OFF_SW;   // 80 x 132
#pragma unroll 1
    for (int ocg = 0; ocg < 4; ocg++) {
        __syncthreads();
        if (wm == ocg) {
#pragma unroll
            for (int mt = 0; mt < 5; mt++)
#pragma unroll
                for (int nt = 0; nt < 8; nt++)
#pragma unroll
                    for (int j = 0; j < 4; j++) {
                        int row = mt * 16 + r4 + 8 * (j >> 1);
                        int col = wn * 64 + nt * 8 + 2 * q + (j & 1);
                        fE[row * 132 + col] =
                            to_tf32(acc[mt][nt][j] + fB[ocg * 80 + row]);
                    }
        }
        __syncthreads();

        if (ocg == 0) {
            // rows 0..63: q/k -> [n][o-perm]; rows 64..79: v c=0..15
#pragma unroll
            for (int i = 0; i < 2; i++) {
                int item = tid + i * 256;
                if (item < 256) {
                    int n = item & 127, half = item >> 7;
                    float vv[32];
#pragma unroll
                    for (int o = 0; o < 32; o++)
                        vv[o] = fE[(half * 32 + o) * 132 + n];
                    float* dst = (half ? g_kt : g_qt) + ((size_t)b * NN + n0 + n) * CQK;
#pragma unroll
                    for (int og = 0; og < 4; og++) {
                        *(float4*)(dst + og * 8) =
                            make_float4(vv[og*8+0], vv[og*8+4], vv[og*8+1], vv[og*8+5]);
                        *(float4*)(dst + og * 8 + 4) =
                            make_float4(vv[og*8+2], vv[og*8+6], vv[og*8+3], vv[og*8+7]);
                    }
                } else {
                    int it = item - 256;
                    int row = 64 + (it >> 4), g = it & 15;
                    int c = row - 64;
                    const float* base = fE + row * 132 + g * 8;
                    float* d = g_v + ((size_t)b * CC + c) * NN + n0 + g * 8;
                    *(float4*)d       = make_float4(base[0], base[4], base[1], base[5]);
                    *(float4*)(d + 4) = make_float4(base[2], base[6], base[3], base[7]);
                }
            }
        } else {
            // all 80 rows are v: c = ocg*80 + row - 64
#pragma unroll
            for (int i = 0; i < 5; i++) {
                int item = tid + i * 256;
                int row = item >> 4, g = item & 15;
                int c = ocg * 80 + row - 64;
                const float* base = fE + row * 132 + g * 8;
                float* d = g_v + ((size_t)b * CC + c) * NN + n0 + g * 8;
                *(float4*)d       = make_float4(base[0], base[4], base[1], base[5]);
                *(float4*)(d + 4) = make_float4(base[2], base[6], base[3], base[7]);
            }
        }
    }
}

// ===========================================================================
// 2) Flash attention (R6 version, best known): per block (b, 128-row n-tile),
//    m-tiles of 64; scores -> in-warp online softmax -> P smem -> out MMA.
//    LOG2E applied to q fragments at load.
// ===========================================================================
__global__ __launch_bounds__(256, 1) void flash_kernel(const float* __restrict__ x,
                                                       float* __restrict__ out) {
    extern __shared__ float sm[];

    const int b   = blockIdx.y;
    const int n0  = blockIdx.x * 128;
    const int tid = threadIdx.x;
    const int wid = tid >> 5, lane = tid & 31;
    const int r4 = lane >> 2, q = lane & 3;
    const int wr = wid >> 2, wc = wid & 3;

    const unsigned sb  = smem_u32(sm);
    const unsigned sQ  = sb + OFF_Q * 4;
    const unsigned sK  = sb + OFF_K * 4;
    const unsigned sV  = sb + OFF_V * 4;
    const unsigned sP  = sb + OFF_P * 4;
    float* fP  = sm + OFF_P;
    float* fSC = sm + OFF_SC;
    float* fL  = sm + OFF_L;

    const float* qg = g_qt + ((size_t)b * NN + n0) * CQK;
    const float* kg0 = g_kt + (size_t)b * NN * CQK;
    const float* vg0 = g_v  + (size_t)b * CC * NN;

    // ---- prologue: q tile + first K/V tiles via cp.async
#pragma unroll
    for (int i = 0; i < 4; i++) {
        int idx = tid + i * 256;
        int row = idx >> 3, p = idx & 7;
        cp16(sQ + (unsigned)(row * 40 + p * 4) * 4, qg + (size_t)row * CQK + p * 4);
    }
    {
#pragma unroll
        for (int i = 0; i < 2; i++) {
            int idx = tid + i * 256;
            int row = idx >> 3, p = idx & 7;
            cp16(sK + (unsigned)(row * 40 + p * 4) * 4, kg0 + (size_t)row * CQK + p * 4);
        }
#pragma unroll
        for (int i = 0; i < 16; i++) {
            int idx = tid + i * 256;
            int row = idx >> 4, p = idx & 15;
            cp16(sV + (unsigned)(row * 72 + p * 4) * 4, vg0 + (size_t)row * NN + p * 4);
        }
    }
    CP_COMMIT();
    CP_WAIT(0);
    __syncthreads();

    // q fragments (whole kernel): warp owns rows 16*wid..+15; scale by LOG2E
    const int rowS = 16 * wid + r4;
    unsigned qf[4][4];
#pragma unroll
    for (int kk = 0; kk < 4; kk++) {
        unsigned ad = sQ + (unsigned)(rowS * 40 + kk * 8 + 2 * q) * 4;
        lds2(ad,             qf[kk][0], qf[kk][2]);
        lds2(ad + 8 * 40 * 4, qf[kk][1], qf[kk][3]);
    }
#pragma unroll
    for (int kk = 0; kk < 4; kk++)
#pragma unroll
        for (int j = 0; j < 4; j++)
            qf[kk][j] = __float_as_uint(to_tf32(LOG2E * __uint_as_float(qf[kk][j])));

    float acc[4][8][4];
#pragma unroll
    for (int mt = 0; mt < 4; mt++)
#pragma unroll
        for (int nt = 0; nt < 8; nt++)
#pragma unroll
            for (int j = 0; j < 4; j++) acc[mt][nt][j] = 0.f;

    float mA = -1e30f, mB = -1e30f, lA = 0.f, lB = 0.f;

    const int STEPS = NN / 64;
    for (int s = 0; s < STEPS; s++) {
        if (s > 0) CP_WAIT(0);
        __syncthreads();   // K/V buf(s) visible; P(s-1) fully consumed

        if (s + 1 < STEPS) {
            const int m1 = (s + 1) * 64;
            const unsigned kd = sK + (unsigned)((s + 1) & 1) * (64 * 40 * 4);
            const float* kg = kg0 + (size_t)m1 * CQK;
#pragma unroll
            for (int i = 0; i < 2; i++) {
                int idx = tid + i * 256;
                int row = idx >> 3, p = idx & 7;
                cp16(kd + (unsigned)(row * 40 + p * 4) * 4, kg + (size_t)row * CQK + p * 4);
            }
            const unsigned vd = sV + (unsigned)((s + 1) & 1) * (256 * 72 * 4);
#pragma unroll
            for (int i = 0; i < 16; i++) {
                int idx = tid + i * 256;
                int row = idx >> 4, p = idx & 15;
                cp16(vd + (unsigned)(row * 72 + p * 4) * 4,
                     vg0 + (size_t)row * NN + m1 + p * 4);
            }
            CP_COMMIT();
        }

        // ---- scores: 16 rows x 64 m per warp
        const unsigned kbuf = sK + (unsigned)(s & 1) * (64 * 40 * 4);
        float sacc[8][4];
#pragma unroll
        for (int nt = 0; nt < 8; nt++)
#pragma unroll
            for (int j = 0; j < 4; j++) sacc[nt][j] = 0.f;

#pragma unroll
        for (int kk = 0; kk < 4; kk++) {
            unsigned kb[8][2];
#pragma unroll
            for (int nt = 0; nt < 8; nt++)
                lds2(kbuf + (unsigned)((nt * 8 + r4) * 40 + kk * 8 + 2 * q) * 4,
                     kb[nt][0], kb[nt][1]);
#pragma unroll
            for (int nt = 0; nt < 8; nt++)
                mma8(sacc[nt], qf[kk][0], qf[kk][1], qf[kk][2], qf[kk][3],
                     kb[nt][0], kb[nt][1]);
        }

        // ---- online softmax stats (base-2)
        float rmA = sacc[0][0], rmB = sacc[0][2];
#pragma unroll
        for (int nt = 0; nt < 8; nt++) {
            rmA = fmaxf(rmA, fmaxf(sacc[nt][0], sacc[nt][1]));
            rmB = fmaxf(rmB, fmaxf(sacc[nt][2], sacc[nt][3]));
        }
#pragma unroll
        for (int off = 1; off <= 2; off <<= 1) {
            rmA = fmaxf(rmA, __shfl_xor_sync(0xffffffffu, rmA, off));
            rmB = fmaxf(rmB, __shfl_xor_sync(0xffffffffu, rmB, off));
        }
        const float mnA = fmaxf(mA, rmA), mnB = fmaxf(mB, rmB);
        const float scA = ex2(mA - mnA),  scB = ex2(mB - mnB);
        mA = mnA; mB = mnB;

        float lsA = 0.f, lsB = 0.f;
#pragma unroll
        for (int nt = 0; nt < 8; nt++) {
            float p0 = to_tf32(ex2(sacc[nt][0] - mnA));
            float p1 = to_tf32(ex2(sacc[nt][1] - mnA));
            float p2 = to_tf32(ex2(sacc[nt][2] - mnB));
            float p3 = to_tf32(ex2(sacc[nt][3] - mnB));
            sacc[nt][0] = p0; sacc[nt][1] = p1; sacc[nt][2] = p2; sacc[nt][3] = p3;
            lsA += p0 + p1; lsB += p2 + p3;
        }
#pragma unroll
        for (int off = 1; off <= 2; off <<= 1) {
            lsA += __shfl_xor_sync(0xffffffffu, lsA, off);
            lsB += __shfl_xor_sync(0xffffffffu, lsB, off);
        }
        lA = lA * scA + lsA;
        lB = lB * scB + lsB;

        // ---- P -> smem (k-permuted cols for v2 operand loads)
#pragma unroll
        for (int nt = 0; nt < 8; nt++) {
#pragma unroll
            for (int j = 0; j < 4; j++) {
                int k = 2 * q + (j & 1);
                int pos = 2 * (k & 3) + (k >> 2);
                int row = rowS + 8 * (j >> 1);
                fP[row * 72 + nt * 8 + pos] = sacc[nt][j];
            }
        }
        if (q == 0) { fSC[rowS] = scA; fSC[rowS + 8] = scB; }
        __syncthreads();

        // ---- rescale out accumulator (vote-skip when max unchanged)
        float scr[8];
#pragma unroll
        for (int mt = 0; mt < 4; mt++) {
            scr[2 * mt]     = fSC[wr * 64 + mt * 16 + r4];
            scr[2 * mt + 1] = fSC[wr * 64 + mt * 16 + r4 + 8];
        }
        bool ones = true;
#pragma unroll
        for (int k = 0; k < 8; k++) ones = ones && (scr[k] == 1.0f);
        if (!__all_sync(0xffffffffu, ones)) {
#pragma unroll
            for (int mt = 0; mt < 4; mt++)
#pragma unroll
                for (int nt = 0; nt < 8; nt++) {
                    acc[mt][nt][0] *= scr[2 * mt];
                    acc[mt][nt][1] *= scr[2 * mt];
                    acc[mt][nt][2] *= scr[2 * mt + 1];
                    acc[mt][nt][3] *= scr[2 * mt + 1];
                }
        }

        // ---- out MMA: acc[n 64(wr) x c 64(wc)] += P @ V^T over m=64
        const unsigned vbuf = sV + (unsigned)(s & 1) * (256 * 72 * 4);
#pragma unroll
        for (int kk = 0; kk < 8; kk++) {
            unsigned af[4][4], bf[8][2];
#pragma unroll
            for (int mt = 0; mt < 4; mt++) {
                unsigned ad = sP + (unsigned)((wr * 64 + mt * 16 + r4) * 72 + kk * 8 + 2 * q) * 4;
                lds2(ad,             af[mt][0], af[mt][2]);
                lds2(ad + 8 * 72 * 4, af[mt][1], af[mt][3]);
            }
#pragma unroll
            for (int nt = 0; nt < 8; nt++)
                lds2(vbuf + (unsigned)((wc * 64 + nt * 8 + r4) * 72 + kk * 8 + 2 * q) * 4,
                     bf[nt][0], bf[nt][1]);
#pragma unroll
            for (int mt = 0; mt < 4; mt++)
#pragma unroll
                for (int nt = 0; nt < 8; nt++)
                    mma8(acc[mt][nt], af[mt][0], af[mt][1], af[mt][2], af[mt][3],
                         bf[nt][0], bf[nt][1]);
        }
    }

    // ---- finalize: /l
    if (q == 0) { fL[rowS] = lA; fL[rowS + 8] = lB; }
    __syncthreads();
    float linv[8];
#pragma unroll
    for (int mt = 0; mt < 4; mt++) {
        linv[2 * mt]     = 1.f / fL[wr * 64 + mt * 16 + r4];
        linv[2 * mt + 1] = 1.f / fL[wr * 64 + mt * 16 + r4 + 8];
    }
#pragma unroll
    for (int mt = 0; mt < 4; mt++)
#pragma unroll
        for (int nt = 0; nt < 8; nt++) {
            acc[mt][nt][0] *= linv[2 * mt];
            acc[mt][nt][1] *= linv[2 * mt];
            acc[mt][nt][2] *= linv[2 * mt + 1];
            acc[mt][nt][3] *= linv[2 * mt + 1];
        }

    // ---- epilogue: transpose n x c -> c x n via smem (reuse V area), +x, store
    float* fT = sm + OFF_V;   // 128 x 132
    const float* xb = x   + (size_t)b * CC * NN + n0;
    float*       ob = out + (size_t)b * CC * NN + n0;
#pragma unroll 1
    for (int ch = 0; ch < 2; ch++) {
        __syncthreads();
        if ((wc >> 1) == ch) {
#pragma unroll
            for (int mt = 0; mt < 4; mt++)
#pragma unroll
                for (int nt = 0; nt < 8; nt++)
#pragma unroll
                    for (int j = 0; j < 4; j++) {
                        int cl = (wc & 1) * 64 + nt * 8 + 2 * q + (j & 1);
                        int rn = wr * 64 + mt * 16 + r4 + 8 * (j >> 1);
                        fT[cl * 132 + rn] = acc[mt][nt][j];
                    }
        }
        __syncthreads();
#pragma unroll
        for (int i = 0; i < 16; i++) {
            int idx = tid + i * 256;
            int cr = idx >> 5;
            int n4 = (idx & 31) * 4;
            float4 t = *(const float4*)&fT[cr * 132 + n4];
            const size_t go = (size_t)(ch * 128 + cr) * NN + n4;
            float4 xv = *(const float4*)(xb + go);
            *(float4*)(ob + go) = make_float4(t.x + xv.x, t.y + xv.y,
                                              t.z + xv.z, t.w + xv.w);
        }
    }
}

// ===========================================================================
extern "C" void kernel_launch(void* const* d_in, const int* in_sizes, int n_in,
                              void* d_out, int out_size) {
    const float* x  = (const float*)d_in[0];
    const float* Wq = (const float*)d_in[1];
    const float* bq = (const float*)d_in[2];
    const float* Wk = (const float*)d_in[3];
    const float* bk = (const float*)d_in[4];
    const float* Wv = (const float*)d_in[5];
    const float* bv = (const float*)d_in[6];
    float* out = (float*)d_out;

    const int pdyn = P_SMEM_FLOATS * 4;   // 130304 B
    cudaFuncSetAttribute(proj_fused_kernel,
                         cudaFuncAttributeMaxDynamicSharedMemorySize, pdyn);
    proj_fused_kernel<<<dim3(NN / 128, BB), 256, pdyn>>>(x, Wq, bq, Wk, bk, Wv, bv);

    const int fdyn = SMEM_FLOATS * 4;     // 226304 B
    cudaFuncSetAttribute(flash_kernel,
                         cudaFuncAttributeMaxDynamicSharedMemorySize, fdyn);
    flash_kernel<<<dim3(NN / 128, BB), 256, fdyn>>>(x, out);
}

// round 9
// speedup vs baseline: 1.4039x; 1.0435x over previous
#include <cuda_runtime.h>

#define BB  4
#define CC  256
#define CQK 32
#define NN  4096
#define LOG2E 1.4426950408889634f

// q/k: [b][n][c-perm] (perm in 8-groups [k0,k4,k1,k5,k2,k6,k3,k7]), tf32.
// v: [b][c][m-perm], tf32.  (LOG2E applied to q inside flash kernel.)
__device__ float g_qt[BB * NN * CQK];
__device__ float g_kt[BB * NN * CQK];
__device__ float g_v [BB * CC * NN];

// ---- flash smem layout (floats)
#define OFF_Q  0            // 128 x 40
#define OFF_K  5120         // 2 x 64 x 40
#define OFF_V  10240        // 2 x 256 x 72
#define SMEM_FLOATS 47104   // 188416 bytes; epilogue fT 256x132=33792 reuses OFF_V

// ---- proj smem layout (floats)
#define P_OFF_SX 0          // 2 x 128 x 36
#define P_OFF_SW 9216       // 2 x 320 x 36
#define P_OFF_SB 32256      // 320
#define P_SMEM_FLOATS 32576 // 130304 bytes (epilogue 80x132 reuses P_OFF_SW)

// ===========================================================================
__device__ __forceinline__ unsigned smem_u32(const void* p) {
    unsigned a;
    asm("{ .reg .u64 t; cvta.to.shared.u64 t, %1; cvt.u32.u64 %0, t; }"
        : "=r"(a) : "l"(p));
    return a;
}
__device__ __forceinline__ float to_tf32(float x) {
    unsigned u;
    asm("cvt.rna.tf32.f32 %0, %1;" : "=r"(u) : "f"(x));
    return __uint_as_float(u);
}
__device__ __forceinline__ float ex2(float x) {
    float y;
    asm("ex2.approx.ftz.f32 %0, %1;" : "=f"(y) : "f"(x));
    return y;
}
__device__ __forceinline__ void cp16(unsigned dst, const void* src) {
    asm volatile("cp.async.cg.shared.global [%0], [%1], 16;" :: "r"(dst), "l"(src));
}
__device__ __forceinline__ void cp4(unsigned dst, const void* src) {
    asm volatile("cp.async.ca.shared.global [%0], [%1], 4;" :: "r"(dst), "l"(src));
}
#define CP_COMMIT()  asm volatile("cp.async.commit_group;")
#define CP_WAIT(n)   asm volatile("cp.async.wait_group %0;" :: "n"(n))

__device__ __forceinline__ void lds2(unsigned addr, unsigned& x, unsigned& y) {
    asm volatile("ld.shared.v2.b32 {%0, %1}, [%2];" : "=r"(x), "=r"(y) : "r"(addr));
}
__device__ __forceinline__ unsigned lds1(unsigned addr) {
    unsigned v;
    asm volatile("ld.shared.b32 %0, [%1];" : "=r"(v) : "r"(addr));
    return v;
}
__device__ __forceinline__ void mma8(float c[4],
                                     unsigned a0, unsigned a1, unsigned a2, unsigned a3,
                                     unsigned b0, unsigned b1) {
    asm volatile(
        "mma.sync.aligned.m16n8k8.row.col.f32.tf32.tf32.f32 "
        "{%0,%1,%2,%3}, {%4,%5,%6,%7}, {%8,%9}, {%0,%1,%2,%3};"
        : "+f"(c[0]), "+f"(c[1]), "+f"(c[2]), "+f"(c[3])
        : "r"(a0), "r"(a1), "r"(a2), "r"(a3), "r"(b0), "r"(b1));
}

// ===========================================================================
// 1) Fused q+k+v projection via tensor cores (R8, unchanged).
// ===========================================================================
__global__ __launch_bounds__(256, 1) void proj_fused_kernel(
        const float* __restrict__ x,
        const float* __restrict__ Wq, const float* __restrict__ bq,
        const float* __restrict__ Wk, const float* __restrict__ bk,
        const float* __restrict__ Wv, const float* __restrict__ bv) {
    extern __shared__ float psm[];

    const int b   = blockIdx.y;
    const int n0  = blockIdx.x * 128;
    const int tid = threadIdx.x;
    const int wid = tid >> 5, lane = tid & 31;
    const int r4 = lane >> 2, q = lane & 3;
    const int wm = wid >> 1, wn = wid & 1;

    const unsigned sb4 = smem_u32(psm);
    const unsigned sX  = sb4 + P_OFF_SX * 4;
    const unsigned sW  = sb4 + P_OFF_SW * 4;
    float* fB = psm + P_OFF_SB;

    {
        int i = tid;
        if (i < 32) fB[i] = bq[i];
        else if (i < 64) fB[i] = bk[i - 32];
        else fB[i] = bv[i - 64];
        i = tid + 256;
        if (i < 320) fB[i] = bv[i - 64];
    }

    auto issue = [&](int ch) {
        const int buf = ch & 1;
        const unsigned wd = sW + (unsigned)buf * (320 * 36 * 4);
#pragma unroll
        for (int i = 0; i < 10; i++) {
            int idx = tid + i * 256;
            int row = idx >> 3, seg = idx & 7;
            int c = ch * 32 + seg * 4;
            const float* src = (row < 32) ? (Wq + row * 256 + c)
                             : (row < 64) ? (Wk + (row - 32) * 256 + c)
                                          : (Wv + (row - 64) * 256 + c);
            cp16(wd + (unsigned)(row * 36 + seg * 4) * 4, src);
        }
        const unsigned xd = sX + (unsigned)buf * (128 * 36 * 4);
#pragma unroll
        for (int i = 0; i < 16; i++) {
            int idx = tid + i * 256;
            int c = idx >> 7, n = idx & 127;
            cp4(xd + (unsigned)(n * 36 + c) * 4,
                x + ((size_t)b * CC + ch * 32 + c) * NN + n0 + n);
        }
        CP_COMMIT();
    };

    float acc[5][8][4];
#pragma unroll
    for (int mt = 0; mt < 5; mt++)
#pragma unroll
        for (int nt = 0; nt < 8; nt++)
#pragma unroll
            for (int j = 0; j < 4; j++) acc[mt][nt][j] = 0.f;

    issue(0);
    for (int ch = 0; ch < 8; ch++) {
        if (ch < 7) { issue(ch + 1); CP_WAIT(1); }
        else        { CP_WAIT(0); }
        __syncthreads();

        const int buf = ch & 1;
        const unsigned swb = sW + (unsigned)buf * (320 * 36 * 4);
        const unsigned sxb = sX + (unsigned)buf * (128 * 36 * 4);
#pragma unroll
        for (int kk = 0; kk < 4; kk++) {
            unsigned a[5][4];
#pragma unroll
            for (int mt = 0; mt < 5; mt++) {
                unsigned base = swb + (unsigned)((wm * 80 + mt * 16 + r4) * 36 + kk * 8 + q) * 4;
                a[mt][0] = lds1(base);
                a[mt][1] = lds1(base + 8 * 36 * 4);
                a[mt][2] = lds1(base + 16);
                a[mt][3] = lds1(base + 8 * 36 * 4 + 16);
            }
            unsigned bb[8][2];
#pragma unroll
            for (int nt = 0; nt < 8; nt++) {
                unsigned nb = sxb + (unsigned)((wn * 64 + nt * 8 + r4) * 36 + kk * 8 + q) * 4;
                bb[nt][0] = lds1(nb);
                bb[nt][1] = lds1(nb + 16);
            }
#pragma unroll
            for (int mt = 0; mt < 5; mt++)
#pragma unroll
                for (int nt = 0; nt < 8; nt++)
                    mma8(acc[mt][nt], a[mt][0], a[mt][1], a[mt][2], a[mt][3],
                         bb[nt][0], bb[nt][1]);
        }
        __syncthreads();
    }

    float* fE = psm + P_OFF_SW;   // 80 x 132
#pragma unroll 1
    for (int ocg = 0; ocg < 4; ocg++) {
        __syncthreads();
        if (wm == ocg) {
#pragma unroll
            for (int mt = 0; mt < 5; mt++)
#pragma unroll
                for (int nt = 0; nt < 8; nt++)
#pragma unroll
                    for (int j = 0; j < 4; j++) {
                        int row = mt * 16 + r4 + 8 * (j >> 1);
                        int col = wn * 64 + nt * 8 + 2 * q + (j & 1);
                        fE[row * 132 + col] =
                            to_tf32(acc[mt][nt][j] + fB[ocg * 80 + row]);
                    }
        }
        __syncthreads();

        if (ocg == 0) {
#pragma unroll
            for (int i = 0; i < 2; i++) {
                int item = tid + i * 256;
                if (item < 256) {
                    int n = item & 127, half = item >> 7;
                    float vv[32];
#pragma unroll
                    for (int o = 0; o < 32; o++)
                        vv[o] = fE[(half * 32 + o) * 132 + n];
                    float* dst = (half ? g_kt : g_qt) + ((size_t)b * NN + n0 + n) * CQK;
#pragma unroll
                    for (int og = 0; og < 4; og++) {
                        *(float4*)(dst + og * 8) =
                            make_float4(vv[og*8+0], vv[og*8+4], vv[og*8+1], vv[og*8+5]);
                        *(float4*)(dst + og * 8 + 4) =
                            make_float4(vv[og*8+2], vv[og*8+6], vv[og*8+3], vv[og*8+7]);
                    }
                } else {
                    int it = item - 256;
                    int row = 64 + (it >> 4), g = it & 15;
                    int c = row - 64;
                    const float* base = fE + row * 132 + g * 8;
                    float* d = g_v + ((size_t)b * CC + c) * NN + n0 + g * 8;
                    *(float4*)d       = make_float4(base[0], base[4], base[1], base[5]);
                    *(float4*)(d + 4) = make_float4(base[2], base[6], base[3], base[7]);
                }
            }
        } else {
#pragma unroll
            for (int i = 0; i < 5; i++) {
                int item = tid + i * 256;
                int row = item >> 4, g = item & 15;
                int c = ocg * 80 + row - 64;
                const float* base = fE + row * 132 + g * 8;
                float* d = g_v + ((size_t)b * CC + c) * NN + n0 + g * 8;
                *(float4*)d       = make_float4(base[0], base[4], base[1], base[5]);
                *(float4*)(d + 4) = make_float4(base[2], base[6], base[3], base[7]);
            }
        }
    }
}

// ===========================================================================
// 2) Flash attention, warp-autonomous: each warp owns 16 n-rows x 256 c.
//    P stays in registers (shfl-built A-frags), softmax/rescale/l warp-local,
//    ONE __syncthreads per step (K/V rotation). m-tiles of 64.
// ===========================================================================
__global__ __launch_bounds__(256, 1) void flash_kernel(const float* __restrict__ x,
                                                       float* __restrict__ out) {
    extern __shared__ float sm[];

    const int b   = blockIdx.y;
    const int n0  = blockIdx.x * 128;
    const int tid = threadIdx.x;
    const int wid = tid >> 5, lane = tid & 31;
    const int r4 = lane >> 2, q = lane & 3;

    const unsigned sb  = smem_u32(sm);
    const unsigned sQ  = sb + OFF_Q * 4;
    const unsigned sK  = sb + OFF_K * 4;
    const unsigned sV  = sb + OFF_V * 4;

    const float* qg  = g_qt + ((size_t)b * NN + n0) * CQK;
    const float* kg0 = g_kt + (size_t)b * NN * CQK;
    const float* vg0 = g_v  + (size_t)b * CC * NN;

    // ---- prologue: q tile + first K/V tiles via cp.async
#pragma unroll
    for (int i = 0; i < 4; i++) {
        int idx = tid + i * 256;
        int row = idx >> 3, p = idx & 7;
        cp16(sQ + (unsigned)(row * 40 + p * 4) * 4, qg + (size_t)row * CQK + p * 4);
    }
    {
#pragma unroll
        for (int i = 0; i < 2; i++) {
            int idx = tid + i * 256;
            int row = idx >> 3, p = idx & 7;
            cp16(sK + (unsigned)(row * 40 + p * 4) * 4, kg0 + (size_t)row * CQK + p * 4);
        }
#pragma unroll
        for (int i = 0; i < 16; i++) {
            int idx = tid + i * 256;
            int row = idx >> 4, p = idx & 15;
            cp16(sV + (unsigned)(row * 72 + p * 4) * 4, vg0 + (size_t)row * NN + p * 4);
        }
    }
    CP_COMMIT();
    CP_WAIT(0);
    __syncthreads();

    // q fragments: warp owns rows 16*wid..+15; fold LOG2E
    const int rowS = 16 * wid + r4;
    unsigned qf[4][4];
#pragma unroll
    for (int kk = 0; kk < 4; kk++) {
        unsigned ad = sQ + (unsigned)(rowS * 40 + kk * 8 + 2 * q) * 4;
        lds2(ad,              qf[kk][0], qf[kk][2]);
        lds2(ad + 8 * 40 * 4, qf[kk][1], qf[kk][3]);
    }
#pragma unroll
    for (int kk = 0; kk < 4; kk++)
#pragma unroll
        for (int j = 0; j < 4; j++)
            qf[kk][j] = __float_as_uint(to_tf32(LOG2E * __uint_as_float(qf[kk][j])));

    // out accumulator: 16 rows x 256 c -> 32 nt fragments
    float acc[32][4];
#pragma unroll
    for (int nt = 0; nt < 32; nt++)
#pragma unroll
        for (int j = 0; j < 4; j++) acc[nt][j] = 0.f;

    float mA = -1e30f, mB = -1e30f, lA = 0.f, lB = 0.f;

    // shuffle source lanes for A-frag build
    const int l0 = (lane & 28) | (q >> 1);
    const int l1 = l0 + 2;
    const bool hi = (q & 1) != 0;

    const int STEPS = NN / 64;
    for (int s = 0; s < STEPS; s++) {
        if (s > 0) CP_WAIT(0);
        __syncthreads();   // K/V buf(s) visible; buf(s^1) reads finished

        if (s + 1 < STEPS) {
            const int m1 = (s + 1) * 64;
            const unsigned kd = sK + (unsigned)((s + 1) & 1) * (64 * 40 * 4);
            const float* kg = kg0 + (size_t)m1 * CQK;
#pragma unroll
            for (int i = 0; i < 2; i++) {
                int idx = tid + i * 256;
                int row = idx >> 3, p = idx & 7;
                cp16(kd + (unsigned)(row * 40 + p * 4) * 4, kg + (size_t)row * CQK + p * 4);
            }
            const unsigned vd = sV + (unsigned)((s + 1) & 1) * (256 * 72 * 4);
#pragma unroll
            for (int i = 0; i < 16; i++) {
                int idx = tid + i * 256;
                int row = idx >> 4, p = idx & 15;
                cp16(vd + (unsigned)(row * 72 + p * 4) * 4,
                     vg0 + (size_t)row * NN + m1 + p * 4);
            }
            CP_COMMIT();
        }

        // ---- scores: own 16 rows x 64 m
        const unsigned kbuf = sK + (unsigned)(s & 1) * (64 * 40 * 4);
        float sacc[8][4];
#pragma unroll
        for (int nt = 0; nt < 8; nt++)
#pragma unroll
            for (int j = 0; j < 4; j++) sacc[nt][j] = 0.f;

#pragma unroll
        for (int kk = 0; kk < 4; kk++) {
            unsigned kb[8][2];
#pragma unroll
            for (int nt = 0; nt < 8; nt++)
                lds2(kbuf + (unsigned)((nt * 8 + r4) * 40 + kk * 8 + 2 * q) * 4,
                     kb[nt][0], kb[nt][1]);
#pragma unroll
            for (int nt = 0; nt < 8; nt++)
                mma8(sacc[nt], qf[kk][0], qf[kk][1], qf[kk][2], qf[kk][3],
                     kb[nt][0], kb[nt][1]);
        }

        // ---- online softmax (warp-local, base-2)
        float rmA = sacc[0][0], rmB = sacc[0][2];
#pragma unroll
        for (int nt = 0; nt < 8; nt++) {
            rmA = fmaxf(rmA, fmaxf(sacc[nt][0], sacc[nt][1]));
            rmB = fmaxf(rmB, fmaxf(sacc[nt][2], sacc[nt][3]));
        }
#pragma unroll
        for (int off = 1; off <= 2; off <<= 1) {
            rmA = fmaxf(rmA, __shfl_xor_sync(0xffffffffu, rmA, off));
            rmB = fmaxf(rmB, __shfl_xor_sync(0xffffffffu, rmB, off));
        }
        const float mnA = fmaxf(mA, rmA), mnB = fmaxf(mB, rmB);
        const float scA = ex2(mA - mnA),  scB = ex2(mB - mnB);
        mA = mnA; mB = mnB;

        float lsA = 0.f, lsB = 0.f;
#pragma unroll
        for (int nt = 0; nt < 8; nt++) {
            float p0 = to_tf32(ex2(sacc[nt][0] - mnA));
            float p1 = to_tf32(ex2(sacc[nt][1] - mnA));
            float p2 = to_tf32(ex2(sacc[nt][2] - mnB));
            float p3 = to_tf32(ex2(sacc[nt][3] - mnB));
            sacc[nt][0] = p0; sacc[nt][1] = p1; sacc[nt][2] = p2; sacc[nt][3] = p3;
            lsA += p0 + p1; lsB += p2 + p3;
        }
#pragma unroll
        for (int off = 1; off <= 2; off <<= 1) {
            lsA += __shfl_xor_sync(0xffffffffu, lsA, off);
            lsB += __shfl_xor_sync(0xffffffffu, lsB, off);
        }
        lA = lA * scA + lsA;
        lB = lB * scB + lsB;

        // ---- rescale acc (warp-local, skip when maxes unchanged)
        if (!__all_sync(0xffffffffu, (scA == 1.f) && (scB == 1.f))) {
#pragma unroll
            for (int nt = 0; nt < 32; nt++) {
                acc[nt][0] *= scA; acc[nt][1] *= scA;
                acc[nt][2] *= scB; acc[nt][3] *= scB;
            }
        }

        // ---- out MMA: acc[16 rows x 256 c] += P @ V^T over m=64
        // A-frags built from sacc via shfl (cols 2q,2q+1 -> q,q+4)
        const unsigned vbuf = sV + (unsigned)(s & 1) * (256 * 72 * 4);
#pragma unroll
        for (int kk = 0; kk < 8; kk++) {
            float t0 = __shfl_sync(0xffffffffu, sacc[kk][0], l0);
            float t1 = __shfl_sync(0xffffffffu, sacc[kk][1], l0);
            float t2 = __shfl_sync(0xffffffffu, sacc[kk][2], l0);
            float t3 = __shfl_sync(0xffffffffu, sacc[kk][3], l0);
            float u0 = __shfl_sync(0xffffffffu, sacc[kk][0], l1);
            float u1 = __shfl_sync(0xffffffffu, sacc[kk][1], l1);
            float u2 = __shfl_sync(0xffffffffu, sacc[kk][2], l1);
            float u3 = __shfl_sync(0xffffffffu, sacc[kk][3], l1);
            unsigned a0 = __float_as_uint(hi ? t1 : t0);
            unsigned a1 = __float_as_uint(hi ? t3 : t2);
            unsigned a2 = __float_as_uint(hi ? u1 : u0);
            unsigned a3 = __float_as_uint(hi ? u3 : u2);
#pragma unroll
            for (int nt = 0; nt < 32; nt++) {
                unsigned b0, b1;
                lds2(vbuf + (unsigned)((nt * 8 + r4) * 72 + kk * 8 + 2 * q) * 4,
                     b0, b1);
                mma8(acc[nt], a0, a1, a2, a3, b0, b1);
            }
        }
    }

    // ---- normalize by l (warp-local)
    const float linvA = 1.f / lA, linvB = 1.f / lB;
#pragma unroll
    for (int nt = 0; nt < 32; nt++) {
        acc[nt][0] *= linvA; acc[nt][1] *= linvA;
        acc[nt][2] *= linvB; acc[nt][3] *= linvB;
    }

    // ---- epilogue: transpose 16n x 256c -> [c][n] via smem (reuse V), +x, store
    float* fT = sm + OFF_V;   // 256 x 132
    __syncthreads();
#pragma unroll
    for (int nt = 0; nt < 32; nt++)
#pragma unroll
        for (int j = 0; j < 4; j++) {
            int cl = nt * 8 + 2 * q + (j & 1);
            int rn = rowS + 8 * (j >> 1);
            fT[cl * 132 + rn] = acc[nt][j];
        }
    __syncthreads();
    const float* xb = x   + (size_t)b * CC * NN + n0;
    float*       ob = out + (size_t)b * CC * NN + n0;
#pragma unroll
    for (int i = 0; i < 32; i++) {
        int idx = tid + i * 256;
        int cr = idx >> 5;
        int n4 = (idx & 31) * 4;
        float4 t = *(const float4*)&fT[cr * 132 + n4];
        const size_t go = (size_t)cr * NN + n4;
        float4 xv = *(const float4*)(xb + go);
        *(float4*)(ob + go) = make_float4(t.x + xv.x, t.y + xv.y,
                                          t.z + xv.z, t.w + xv.w);
    }
}

// ===========================================================================
extern "C" void kernel_launch(void* const* d_in, const int* in_sizes, int n_in,
                              void* d_out, int out_size) {
    const float* x  = (const float*)d_in[0];
    const float* Wq = (const float*)d_in[1];
    const float* bq = (const float*)d_in[2];
    const float* Wk = (const float*)d_in[3];
    const float* bk = (const float*)d_in[4];
    const float* Wv = (const float*)d_in[5];
    const float* bv = (const float*)d_in[6];
    float* out = (float*)d_out;

    const int pdyn = P_SMEM_FLOATS * 4;   // 130304 B
    cudaFuncSetAttribute(proj_fused_kernel,
                         cudaFuncAttributeMaxDynamicSharedMemorySize, pdyn);
    proj_fused_kernel<<<dim3(NN / 128, BB), 256, pdyn>>>(x, Wq, bq, Wk, bk, Wv, bv);

    const int fdyn = SMEM_FLOATS * 4;     // 188416 B
    cudaFuncSetAttribute(flash_kernel,
                         cudaFuncAttributeMaxDynamicSharedMemorySize, fdyn);
    flash_kernel<<<dim3(NN / 128, BB), 256, fdyn>>>(x, out);
}

// round 10
// speedup vs baseline: 1.4674x; 1.0453x over previous
#include <cuda_runtime.h>
#include <cuda_bf16.h>

#define BB  4
#define CC  256
#define CQK 32
#define NN  4096
#define LOG2E 1.4426950408889634f

// q/k: [b][n][c-perm] (perm in 8-groups [k0,k4,k1,k5,k2,k6,k3,k7]), tf32 fp32.
// v: [b][c][m] bf16, WORD-permuted in 8-word groups [w0,w4,w1,w5,w2,w6,w3,w7]
//    (word = 2 adjacent m). LOG2E folded into q inside flash kernel.
__device__ float g_qt[BB * NN * CQK];
__device__ float g_kt[BB * NN * CQK];
__device__ __nv_bfloat16 g_v[(size_t)BB * CC * NN];

// ---- flash smem layout (float slots)
#define OFF_Q  0            // 128 x 40 fp32
#define OFF_K  5120         // 2 x 64 x 40 fp32
#define OFF_V  10240        // 2 x 256 x 40 words (bf16x2)
#define SMEM_FLOATS 44032   // 176128 B; epilogue fT 256x132 fp32 reuses OFF_V

// ---- proj smem layout (floats)
#define P_OFF_SX 0          // 2 x 128 x 36
#define P_OFF_SW 9216       // 2 x 320 x 36
#define P_OFF_SB 32256      // 320
#define P_SMEM_FLOATS 32576 // 130304 bytes (epilogue 80x132 reuses P_OFF_SW)

// ===========================================================================
__device__ __forceinline__ unsigned smem_u32(const void* p) {
    unsigned a;
    asm("{ .reg .u64 t; cvta.to.shared.u64 t, %1; cvt.u32.u64 %0, t; }"
        : "=r"(a) : "l"(p));
    return a;
}
__device__ __forceinline__ float to_tf32(float x) {
    unsigned u;
    asm("cvt.rna.tf32.f32 %0, %1;" : "=r"(u) : "f"(x));
    return __uint_as_float(u);
}
__device__ __forceinline__ float ex2(float x) {
    float y;
    asm("ex2.approx.ftz.f32 %0, %1;" : "=f"(y) : "f"(x));
    return y;
}
// pack two fp32 -> bf16x2 word (lo = first element)
__device__ __forceinline__ unsigned packbf(float lo, float hi) {
    unsigned r;
    asm("cvt.rn.bf16x2.f32 %0, %1, %2;" : "=r"(r) : "f"(hi), "f"(lo));
    return r;
}
__device__ __forceinline__ void cp16(unsigned dst, const void* src) {
    asm volatile("cp.async.cg.shared.global [%0], [%1], 16;" :: "r"(dst), "l"(src));
}
__device__ __forceinline__ void cp4(unsigned dst, const void* src) {
    asm volatile("cp.async.ca.shared.global [%0], [%1], 4;" :: "r"(dst), "l"(src));
}
#define CP_COMMIT()  asm volatile("cp.async.commit_group;")
#define CP_WAIT(n)   asm volatile("cp.async.wait_group %0;" :: "n"(n))

__device__ __forceinline__ void lds2(unsigned addr, unsigned& x, unsigned& y) {
    asm volatile("ld.shared.v2.b32 {%0, %1}, [%2];" : "=r"(x), "=r"(y) : "r"(addr));
}
__device__ __forceinline__ unsigned lds1(unsigned addr) {
    unsigned v;
    asm volatile("ld.shared.b32 %0, [%1];" : "=r"(v) : "r"(addr));
    return v;
}
__device__ __forceinline__ void mma8(float c[4],
                                     unsigned a0, unsigned a1, unsigned a2, unsigned a3,
                                     unsigned b0, unsigned b1) {
    asm volatile(
        "mma.sync.aligned.m16n8k8.row.col.f32.tf32.tf32.f32 "
        "{%0,%1,%2,%3}, {%4,%5,%6,%7}, {%8,%9}, {%0,%1,%2,%3};"
        : "+f"(c[0]), "+f"(c[1]), "+f"(c[2]), "+f"(c[3])
        : "r"(a0), "r"(a1), "r"(a2), "r"(a3), "r"(b0), "r"(b1));
}
__device__ __forceinline__ void mma16bf(float c[4],
                                        unsigned a0, unsigned a1, unsigned a2, unsigned a3,
                                        unsigned b0, unsigned b1) {
    asm volatile(
        "mma.sync.aligned.m16n8k16.row.col.f32.bf16.bf16.f32 "
        "{%0,%1,%2,%3}, {%4,%5,%6,%7}, {%8,%9}, {%0,%1,%2,%3};"
        : "+f"(c[0]), "+f"(c[1]), "+f"(c[2]), "+f"(c[3])
        : "r"(a0), "r"(a1), "r"(a2), "r"(a3), "r"(b0), "r"(b1));
}

// ===========================================================================
// 1) Fused q+k+v projection via tensor cores. q/k epilogue unchanged (tf32,
//    c-perm). v epilogue: bf16 pack + word-perm, natural m order.
// ===========================================================================
__global__ __launch_bounds__(256, 1) void proj_fused_kernel(
        const float* __restrict__ x,
        const float* __restrict__ Wq, const float* __restrict__ bq,
        const float* __restrict__ Wk, const float* __restrict__ bk,
        const float* __restrict__ Wv, const float* __restrict__ bv) {
    extern __shared__ float psm[];

    const int b   = blockIdx.y;
    const int n0  = blockIdx.x * 128;
    const int tid = threadIdx.x;
    const int wid = tid >> 5, lane = tid & 31;
    const int r4 = lane >> 2, q = lane & 3;
    const int wm = wid >> 1, wn = wid & 1;

    const unsigned sb4 = smem_u32(psm);
    const unsigned sX  = sb4 + P_OFF_SX * 4;
    const unsigned sW  = sb4 + P_OFF_SW * 4;
    float* fB = psm + P_OFF_SB;

    {
        int i = tid;
        if (i < 32) fB[i] = bq[i];
        else if (i < 64) fB[i] = bk[i - 32];
        else fB[i] = bv[i - 64];
        i = tid + 256;
        if (i < 320) fB[i] = bv[i - 64];
    }

    auto issue = [&](int ch) {
        const int buf = ch & 1;
        const unsigned wd = sW + (unsigned)buf * (320 * 36 * 4);
#pragma unroll
        for (int i = 0; i < 10; i++) {
            int idx = tid + i * 256;
            int row = idx >> 3, seg = idx & 7;
            int c = ch * 32 + seg * 4;
            const float* src = (row < 32) ? (Wq + row * 256 + c)
                             : (row < 64) ? (Wk + (row - 32) * 256 + c)
                                          : (Wv + (row - 64) * 256 + c);
            cp16(wd + (unsigned)(row * 36 + seg * 4) * 4, src);
        }
        const unsigned xd = sX + (unsigned)buf * (128 * 36 * 4);
#pragma unroll
        for (int i = 0; i < 16; i++) {
            int idx = tid + i * 256;
            int c = idx >> 7, n = idx & 127;
            cp4(xd + (unsigned)(n * 36 + c) * 4,
                x + ((size_t)b * CC + ch * 32 + c) * NN + n0 + n);
        }
        CP_COMMIT();
    };

    float acc[5][8][4];
#pragma unroll
    for (int mt = 0; mt < 5; mt++)
#pragma unroll
        for (int nt = 0; nt < 8; nt++)
#pragma unroll
            for (int j = 0; j < 4; j++) acc[mt][nt][j] = 0.f;

    issue(0);
    for (int ch = 0; ch < 8; ch++) {
        if (ch < 7) { issue(ch + 1); CP_WAIT(1); }
        else        { CP_WAIT(0); }
        __syncthreads();

        const int buf = ch & 1;
        const unsigned swb = sW + (unsigned)buf * (320 * 36 * 4);
        const unsigned sxb = sX + (unsigned)buf * (128 * 36 * 4);
#pragma unroll
        for (int kk = 0; kk < 4; kk++) {
            unsigned a[5][4];
#pragma unroll
            for (int mt = 0; mt < 5; mt++) {
                unsigned base = swb + (unsigned)((wm * 80 + mt * 16 + r4) * 36 + kk * 8 + q) * 4;
                a[mt][0] = lds1(base);
                a[mt][1] = lds1(base + 8 * 36 * 4);
                a[mt][2] = lds1(base + 16);
                a[mt][3] = lds1(base + 8 * 36 * 4 + 16);
            }
            unsigned bb[8][2];
#pragma unroll
            for (int nt = 0; nt < 8; nt++) {
                unsigned nb = sxb + (unsigned)((wn * 64 + nt * 8 + r4) * 36 + kk * 8 + q) * 4;
                bb[nt][0] = lds1(nb);
                bb[nt][1] = lds1(nb + 16);
            }
#pragma unroll
            for (int mt = 0; mt < 5; mt++)
#pragma unroll
                for (int nt = 0; nt < 8; nt++)
                    mma8(acc[mt][nt], a[mt][0], a[mt][1], a[mt][2], a[mt][3],
                         bb[nt][0], bb[nt][1]);
        }
        __syncthreads();
    }

    float* fE = psm + P_OFF_SW;   // 80 x 132
#pragma unroll 1
    for (int ocg = 0; ocg < 4; ocg++) {
        __syncthreads();
        if (wm == ocg) {
#pragma unroll
            for (int mt = 0; mt < 5; mt++)
#pragma unroll
                for (int nt = 0; nt < 8; nt++)
#pragma unroll
                    for (int j = 0; j < 4; j++) {
                        int row = mt * 16 + r4 + 8 * (j >> 1);
                        int col = wn * 64 + nt * 8 + 2 * q + (j & 1);
                        fE[row * 132 + col] =
                            to_tf32(acc[mt][nt][j] + fB[ocg * 80 + row]);
                    }
        }
        __syncthreads();

        if (ocg == 0) {
            // rows 0..63: q/k -> [n][o-perm] fp32; rows 64..79: v c=0..15 bf16
#pragma unroll
            for (int i = 0; i < 2; i++) {
                int item = tid + i * 256;
                if (item < 256) {
                    int n = item & 127, half = item >> 7;
                    float vv[32];
#pragma unroll
                    for (int o = 0; o < 32; o++)
                        vv[o] = fE[(half * 32 + o) * 132 + n];
                    float* dst = (half ? g_kt : g_qt) + ((size_t)b * NN + n0 + n) * CQK;
#pragma unroll
                    for (int og = 0; og < 4; og++) {
                        *(float4*)(dst + og * 8) =
                            make_float4(vv[og*8+0], vv[og*8+4], vv[og*8+1], vv[og*8+5]);
                        *(float4*)(dst + og * 8 + 4) =
                            make_float4(vv[og*8+2], vv[og*8+6], vv[og*8+3], vv[og*8+7]);
                    }
                } else {
                    int it = item - 256;
                    if (it < 128) {
                        int row = 64 + (it >> 3), gt = it & 7;
                        int c = row - 64;
                        const float* f = fE + row * 132 + gt * 16;
                        unsigned w[8];
#pragma unroll
                        for (int p = 0; p < 8; p++) w[p] = packbf(f[2*p], f[2*p+1]);
                        uint4* d = (uint4*)(g_v + ((size_t)b * CC + c) * NN + n0 + gt * 16);
                        d[0] = make_uint4(w[0], w[4], w[1], w[5]);
                        d[1] = make_uint4(w[2], w[6], w[3], w[7]);
                    }
                }
            }
        } else {
            // 80 v rows: c = ocg*80 + row - 64; 8 16-m groups per row
#pragma unroll
            for (int i = 0; i < 3; i++) {
                int item = tid + i * 256;
                if (item < 640) {
                    int row = item >> 3, gt = item & 7;
                    int c = ocg * 80 + row - 64;
                    const float* f = fE + row * 132 + gt * 16;
                    unsigned w[8];
#pragma unroll
                    for (int p = 0; p < 8; p++) w[p] = packbf(f[2*p], f[2*p+1]);
                    uint4* d = (uint4*)(g_v + ((size_t)b * CC + c) * NN + n0 + gt * 16);
                    d[0] = make_uint4(w[0], w[4], w[1], w[5]);
                    d[1] = make_uint4(w[2], w[6], w[3], w[7]);
                }
            }
        }
    }
}

// ===========================================================================
// 2) Flash attention, warp-autonomous (R9 structure): warp owns 16 n-rows x
//    256 c. QK tf32, PV bf16 m16n8k16 (A-frags packed from score C-frags —
//    no shuffles). One __syncthreads per step.
// ===========================================================================
__global__ __launch_bounds__(256, 1) void flash_kernel(const float* __restrict__ x,
                                                       float* __restrict__ out) {
    extern __shared__ float sm[];

    const int b   = blockIdx.y;
    const int n0  = blockIdx.x * 128;
    const int tid = threadIdx.x;
    const int wid = tid >> 5, lane = tid & 31;
    const int r4 = lane >> 2, q = lane & 3;

    const unsigned sb  = smem_u32(sm);
    const unsigned sQ  = sb + OFF_Q * 4;
    const unsigned sK  = sb + OFF_K * 4;
    const unsigned sV  = sb + OFF_V * 4;

    const float* qg  = g_qt + ((size_t)b * NN + n0) * CQK;
    const float* kg0 = g_kt + (size_t)b * NN * CQK;
    const __nv_bfloat16* vg0 = g_v + (size_t)b * CC * NN;

    // ---- prologue: q tile + first K/V tiles via cp.async
#pragma unroll
    for (int i = 0; i < 4; i++) {
        int idx = tid + i * 256;
        int row = idx >> 3, p = idx & 7;
        cp16(sQ + (unsigned)(row * 40 + p * 4) * 4, qg + (size_t)row * CQK + p * 4);
    }
    {
#pragma unroll
        for (int i = 0; i < 2; i++) {
            int idx = tid + i * 256;
            int row = idx >> 3, p = idx & 7;
            cp16(sK + (unsigned)(row * 40 + p * 4) * 4, kg0 + (size_t)row * CQK + p * 4);
        }
#pragma unroll
        for (int i = 0; i < 8; i++) {      // V: 256 rows x 32 words
            int idx = tid + i * 256;
            int row = idx >> 3, p = idx & 7;
            cp16(sV + (unsigned)(row * 40 + p * 4) * 4,
                 vg0 + (size_t)row * NN + p * 8);
        }
    }
    CP_COMMIT();
    CP_WAIT(0);
    __syncthreads();

    // q fragments: warp owns rows 16*wid..+15; fold LOG2E
    const int rowS = 16 * wid + r4;
    unsigned qf[4][4];
#pragma unroll
    for (int kk = 0; kk < 4; kk++) {
        unsigned ad = sQ + (unsigned)(rowS * 40 + kk * 8 + 2 * q) * 4;
        lds2(ad,              qf[kk][0], qf[kk][2]);
        lds2(ad + 8 * 40 * 4, qf[kk][1], qf[kk][3]);
    }
#pragma unroll
    for (int kk = 0; kk < 4; kk++)
#pragma unroll
        for (int j = 0; j < 4; j++)
            qf[kk][j] = __float_as_uint(to_tf32(LOG2E * __uint_as_float(qf[kk][j])));

    // out accumulator: 16 rows x 256 c -> 32 nt fragments
    float acc[32][4];
#pragma unroll
    for (int nt = 0; nt < 32; nt++)
#pragma unroll
        for (int j = 0; j < 4; j++) acc[nt][j] = 0.f;

    float mA = -1e30f, mB = -1e30f, lA = 0.f, lB = 0.f;

    const int STEPS = NN / 64;
    for (int s = 0; s < STEPS; s++) {
        if (s > 0) CP_WAIT(0);
        __syncthreads();   // K/V buf(s) visible; buf(s^1) reads finished

        if (s + 1 < STEPS) {
            const int m1 = (s + 1) * 64;
            const unsigned kd = sK + (unsigned)((s + 1) & 1) * (64 * 40 * 4);
            const float* kg = kg0 + (size_t)m1 * CQK;
#pragma unroll
            for (int i = 0; i < 2; i++) {
                int idx = tid + i * 256;
                int row = idx >> 3, p = idx & 7;
                cp16(kd + (unsigned)(row * 40 + p * 4) * 4, kg + (size_t)row * CQK + p * 4);
            }
            const unsigned vd = sV + (unsigned)((s + 1) & 1) * (256 * 40 * 4);
#pragma unroll
            for (int i = 0; i < 8; i++) {
                int idx = tid + i * 256;
                int row = idx >> 3, p = idx & 7;
                cp16(vd + (unsigned)(row * 40 + p * 4) * 4,
                     vg0 + (size_t)row * NN + m1 + p * 8);
            }
            CP_COMMIT();
        }

        // ---- scores (tf32): own 16 rows x 64 m
        const unsigned kbuf = sK + (unsigned)(s & 1) * (64 * 40 * 4);
        float sacc[8][4];
#pragma unroll
        for (int nt = 0; nt < 8; nt++)
#pragma unroll
            for (int j = 0; j < 4; j++) sacc[nt][j] = 0.f;

#pragma unroll
        for (int kk = 0; kk < 4; kk++) {
            unsigned kb[8][2];
#pragma unroll
            for (int nt = 0; nt < 8; nt++)
                lds2(kbuf + (unsigned)((nt * 8 + r4) * 40 + kk * 8 + 2 * q) * 4,
                     kb[nt][0], kb[nt][1]);
#pragma unroll
            for (int nt = 0; nt < 8; nt++)
                mma8(sacc[nt], qf[kk][0], qf[kk][1], qf[kk][2], qf[kk][3],
                     kb[nt][0], kb[nt][1]);
        }

        // ---- online softmax (warp-local, base-2)
        float rmA = sacc[0][0], rmB = sacc[0][2];
#pragma unroll
        for (int nt = 0; nt < 8; nt++) {
            rmA = fmaxf(rmA, fmaxf(sacc[nt][0], sacc[nt][1]));
            rmB = fmaxf(rmB, fmaxf(sacc[nt][2], sacc[nt][3]));
        }
#pragma unroll
        for (int off = 1; off <= 2; off <<= 1) {
            rmA = fmaxf(rmA, __shfl_xor_sync(0xffffffffu, rmA, off));
            rmB = fmaxf(rmB, __shfl_xor_sync(0xffffffffu, rmB, off));
        }
        const float mnA = fmaxf(mA, rmA), mnB = fmaxf(mB, rmB);
        const float scA = ex2(mA - mnA),  scB = ex2(mB - mnB);
        mA = mnA; mB = mnB;

        float lsA = 0.f, lsB = 0.f;
#pragma unroll
        for (int nt = 0; nt < 8; nt++) {
            float p0 = ex2(sacc[nt][0] - mnA);
            float p1 = ex2(sacc[nt][1] - mnA);
            float p2 = ex2(sacc[nt][2] - mnB);
            float p3 = ex2(sacc[nt][3] - mnB);
            sacc[nt][0] = p0; sacc[nt][1] = p1; sacc[nt][2] = p2; sacc[nt][3] = p3;
            lsA += p0 + p1; lsB += p2 + p3;
        }
#pragma unroll
        for (int off = 1; off <= 2; off <<= 1) {
            lsA += __shfl_xor_sync(0xffffffffu, lsA, off);
            lsB += __shfl_xor_sync(0xffffffffu, lsB, off);
        }
        lA = lA * scA + lsA;
        lB = lB * scB + lsB;

        // ---- rescale acc (warp-local, skip when maxes unchanged)
        if (!__all_sync(0xffffffffu, (scA == 1.f) && (scB == 1.f))) {
#pragma unroll
            for (int nt = 0; nt < 32; nt++) {
                acc[nt][0] *= scA; acc[nt][1] *= scA;
                acc[nt][2] *= scB; acc[nt][3] *= scB;
            }
        }

        // ---- out MMA (bf16 k16): acc[16n x 256c] += P @ V^T over m=64
        // A-frags: pack score C-frags directly (layouts match, no shfl)
        const unsigned vbuf = sV + (unsigned)(s & 1) * (256 * 40 * 4);
#pragma unroll
        for (int g = 0; g < 4; g++) {
            unsigned a0 = packbf(sacc[2*g][0],   sacc[2*g][1]);
            unsigned a1 = packbf(sacc[2*g][2],   sacc[2*g][3]);
            unsigned a2 = packbf(sacc[2*g+1][0], sacc[2*g+1][1]);
            unsigned a3 = packbf(sacc[2*g+1][2], sacc[2*g+1][3]);
#pragma unroll
            for (int nt = 0; nt < 32; nt++) {
                unsigned b0, b1;
                lds2(vbuf + (unsigned)((nt * 8 + r4) * 40 + g * 8 + 2 * q) * 4,
                     b0, b1);
                mma16bf(acc[nt], a0, a1, a2, a3, b0, b1);
            }
        }
    }

    // ---- normalize by l (warp-local)
    const float linvA = 1.f / lA, linvB = 1.f / lB;
#pragma unroll
    for (int nt = 0; nt < 32; nt++) {
        acc[nt][0] *= linvA; acc[nt][1] *= linvA;
        acc[nt][2] *= linvB; acc[nt][3] *= linvB;
    }

    // ---- epilogue: transpose 16n x 256c -> [c][n] via smem (reuse V), +x, store
    float* fT = sm + OFF_V;   // 256 x 132
    __syncthreads();
#pragma unroll
    for (int nt = 0; nt < 32; nt++)
#pragma unroll
        for (int j = 0; j < 4; j++) {
            int cl = nt * 8 + 2 * q + (j & 1);
            int rn = rowS + 8 * (j >> 1);
            fT[cl * 132 + rn] = acc[nt][j];
        }
    __syncthreads();
    const float* xb = x   + (size_t)b * CC * NN + n0;
    float*       ob = out + (size_t)b * CC * NN + n0;
#pragma unroll
    for (int i = 0; i < 32; i++) {
        int idx = tid + i * 256;
        int cr = idx >> 5;
        int n4 = (idx & 31) * 4;
        float4 t = *(const float4*)&fT[cr * 132 + n4];
        const size_t go = (size_t)cr * NN + n4;
        float4 xv = *(const float4*)(xb + go);
        *(float4*)(ob + go) = make_float4(t.x + xv.x, t.y + xv.y,
                                          t.z + xv.z, t.w + xv.w);
    }
}

// ===========================================================================
extern "C" void kernel_launch(void* const* d_in, const int* in_sizes, int n_in,
                              void* d_out, int out_size) {
    const float* x  = (const float*)d_in[0];
    const float* Wq = (const float*)d_in[1];
    const float* bq = (const float*)d_in[2];
    const float* Wk = (const float*)d_in[3];
    const float* bk = (const float*)d_in[4];
    const float* Wv = (const float*)d_in[5];
    const float* bv = (const float*)d_in[6];
    float* out = (float*)d_out;

    const int pdyn = P_SMEM_FLOATS * 4;   // 130304 B
    cudaFuncSetAttribute(proj_fused_kernel,
                         cudaFuncAttributeMaxDynamicSharedMemorySize, pdyn);
    proj_fused_kernel<<<dim3(NN / 128, BB), 256, pdyn>>>(x, Wq, bq, Wk, bk, Wv, bv);

    const int fdyn = SMEM_FLOATS * 4;     // 176128 B
    cudaFuncSetAttribute(flash_kernel,
                         cudaFuncAttributeMaxDynamicSharedMemorySize, fdyn);
    flash_kernel<<<dim3(NN / 128, BB), 256, fdyn>>>(x, out);
}

// round 11
// speedup vs baseline: 1.7777x; 1.2114x over previous
#include <cuda_runtime.h>
#include <cuda_bf16.h>

#define BB  4
#define CC  256
#define CQK 32
#define NN  4096
#define LOG2E 1.4426950408889634f

// q/k: [b][n][c-perm] (perm in 8-groups [k0,k4,k1,k5,k2,k6,k3,k7]), tf32 fp32.
// v: [b][c][m] bf16, WORD-permuted in 8-word groups [w0,w4,w1,w5,w2,w6,w3,w7]
//    (word = 2 adjacent m). LOG2E folded into q inside flash kernel.
__device__ float g_qt[BB * NN * CQK];
__device__ float g_kt[BB * NN * CQK];
__device__ __nv_bfloat16 g_v[(size_t)BB * CC * NN];

// ---- flash smem layout (float slots) — 64-row blocks
#define OFF_Q  0            // 64 x 40 fp32
#define OFF_K  2560         // 2 x 64 x 40 fp32
#define OFF_V  7680         // 2 x 256 x 40 words (bf16x2)
#define SMEM_FLOATS 28160   // 112640 B; epilogue fT 256x68 fp32 reuses OFF_K..

// ---- proj smem layout (floats)
#define P_OFF_SX 0          // 2 x 128 x 36
#define P_OFF_SW 9216       // 2 x 320 x 36
#define P_OFF_SB 32256      // 320
#define P_SMEM_FLOATS 32576 // 130304 bytes (epilogue 80x132 reuses P_OFF_SW)

// ===========================================================================
__device__ __forceinline__ unsigned smem_u32(const void* p) {
    unsigned a;
    asm("{ .reg .u64 t; cvta.to.shared.u64 t, %1; cvt.u32.u64 %0, t; }"
        : "=r"(a) : "l"(p));
    return a;
}
__device__ __forceinline__ float to_tf32(float x) {
    unsigned u;
    asm("cvt.rna.tf32.f32 %0, %1;" : "=r"(u) : "f"(x));
    return __uint_as_float(u);
}
__device__ __forceinline__ float ex2(float x) {
    float y;
    asm("ex2.approx.ftz.f32 %0, %1;" : "=f"(y) : "f"(x));
    return y;
}
// pack two fp32 -> bf16x2 word (lo = first element)
__device__ __forceinline__ unsigned packbf(float lo, float hi) {
    unsigned r;
    asm("cvt.rn.bf16x2.f32 %0, %1, %2;" : "=r"(r) : "f"(hi), "f"(lo));
    return r;
}
__device__ __forceinline__ void cp16(unsigned dst, const void* src) {
    asm volatile("cp.async.cg.shared.global [%0], [%1], 16;" :: "r"(dst), "l"(src));
}
__device__ __forceinline__ void cp4(unsigned dst, const void* src) {
    asm volatile("cp.async.ca.shared.global [%0], [%1], 4;" :: "r"(dst), "l"(src));
}
#define CP_COMMIT()  asm volatile("cp.async.commit_group;")
#define CP_WAIT(n)   asm volatile("cp.async.wait_group %0;" :: "n"(n))

__device__ __forceinline__ void lds2(unsigned addr, unsigned& x, unsigned& y) {
    asm volatile("ld.shared.v2.b32 {%0, %1}, [%2];" : "=r"(x), "=r"(y) : "r"(addr));
}
__device__ __forceinline__ unsigned lds1(unsigned addr) {
    unsigned v;
    asm volatile("ld.shared.b32 %0, [%1];" : "=r"(v) : "r"(addr));
    return v;
}
__device__ __forceinline__ void mma8(float c[4],
                                     unsigned a0, unsigned a1, unsigned a2, unsigned a3,
                                     unsigned b0, unsigned b1) {
    asm volatile(
        "mma.sync.aligned.m16n8k8.row.col.f32.tf32.tf32.f32 "
        "{%0,%1,%2,%3}, {%4,%5,%6,%7}, {%8,%9}, {%0,%1,%2,%3};"
        : "+f"(c[0]), "+f"(c[1]), "+f"(c[2]), "+f"(c[3])
        : "r"(a0), "r"(a1), "r"(a2), "r"(a3), "r"(b0), "r"(b1));
}
__device__ __forceinline__ void mma16bf(float c[4],
                                        unsigned a0, unsigned a1, unsigned a2, unsigned a3,
                                        unsigned b0, unsigned b1) {
    asm volatile(
        "mma.sync.aligned.m16n8k16.row.col.f32.bf16.bf16.f32 "
        "{%0,%1,%2,%3}, {%4,%5,%6,%7}, {%8,%9}, {%0,%1,%2,%3};"
        : "+f"(c[0]), "+f"(c[1]), "+f"(c[2]), "+f"(c[3])
        : "r"(a0), "r"(a1), "r"(a2), "r"(a3), "r"(b0), "r"(b1));
}

// ===========================================================================
// 1) Fused q+k+v projection via tensor cores (R10, unchanged).
// ===========================================================================
__global__ __launch_bounds__(256, 1) void proj_fused_kernel(
        const float* __restrict__ x,
        const float* __restrict__ Wq, const float* __restrict__ bq,
        const float* __restrict__ Wk, const float* __restrict__ bk,
        const float* __restrict__ Wv, const float* __restrict__ bv) {
    extern __shared__ float psm[];

    const int b   = blockIdx.y;
    const int n0  = blockIdx.x * 128;
    const int tid = threadIdx.x;
    const int wid = tid >> 5, lane = tid & 31;
    const int r4 = lane >> 2, q = lane & 3;
    const int wm = wid >> 1, wn = wid & 1;

    const unsigned sb4 = smem_u32(psm);
    const unsigned sX  = sb4 + P_OFF_SX * 4;
    const unsigned sW  = sb4 + P_OFF_SW * 4;
    float* fB = psm + P_OFF_SB;

    {
        int i = tid;
        if (i < 32) fB[i] = bq[i];
        else if (i < 64) fB[i] = bk[i - 32];
        else fB[i] = bv[i - 64];
        i = tid + 256;
        if (i < 320) fB[i] = bv[i - 64];
    }

    auto issue = [&](int ch) {
        const int buf = ch & 1;
        const unsigned wd = sW + (unsigned)buf * (320 * 36 * 4);
#pragma unroll
        for (int i = 0; i < 10; i++) {
            int idx = tid + i * 256;
            int row = idx >> 3, seg = idx & 7;
            int c = ch * 32 + seg * 4;
            const float* src = (row < 32) ? (Wq + row * 256 + c)
                             : (row < 64) ? (Wk + (row - 32) * 256 + c)
                                          : (Wv + (row - 64) * 256 + c);
            cp16(wd + (unsigned)(row * 36 + seg * 4) * 4, src);
        }
        const unsigned xd = sX + (unsigned)buf * (128 * 36 * 4);
#pragma unroll
        for (int i = 0; i < 16; i++) {
            int idx = tid + i * 256;
            int c = idx >> 7, n = idx & 127;
            cp4(xd + (unsigned)(n * 36 + c) * 4,
                x + ((size_t)b * CC + ch * 32 + c) * NN + n0 + n);
        }
        CP_COMMIT();
    };

    float acc[5][8][4];
#pragma unroll
    for (int mt = 0; mt < 5; mt++)
#pragma unroll
        for (int nt = 0; nt < 8; nt++)
#pragma unroll
            for (int j = 0; j < 4; j++) acc[mt][nt][j] = 0.f;

    issue(0);
    for (int ch = 0; ch < 8; ch++) {
        if (ch < 7) { issue(ch + 1); CP_WAIT(1); }
        else        { CP_WAIT(0); }
        __syncthreads();

        const int buf = ch & 1;
        const unsigned swb = sW + (unsigned)buf * (320 * 36 * 4);
        const unsigned sxb = sX + (unsigned)buf * (128 * 36 * 4);
#pragma unroll
        for (int kk = 0; kk < 4; kk++) {
            unsigned a[5][4];
#pragma unroll
            for (int mt = 0; mt < 5; mt++) {
                unsigned base = swb + (unsigned)((wm * 80 + mt * 16 + r4) * 36 + kk * 8 + q) * 4;
                a[mt][0] = lds1(base);
                a[mt][1] = lds1(base + 8 * 36 * 4);
                a[mt][2] = lds1(base + 16);
                a[mt][3] = lds1(base + 8 * 36 * 4 + 16);
            }
            unsigned bb[8][2];
#pragma unroll
            for (int nt = 0; nt < 8; nt++) {
                unsigned nb = sxb + (unsigned)((wn * 64 + nt * 8 + r4) * 36 + kk * 8 + q) * 4;
                bb[nt][0] = lds1(nb);
                bb[nt][1] = lds1(nb + 16);
            }
#pragma unroll
            for (int mt = 0; mt < 5; mt++)
#pragma unroll
                for (int nt = 0; nt < 8; nt++)
                    mma8(acc[mt][nt], a[mt][0], a[mt][1], a[mt][2], a[mt][3],
                         bb[nt][0], bb[nt][1]);
        }
        __syncthreads();
    }

    float* fE = psm + P_OFF_SW;   // 80 x 132
#pragma unroll 1
    for (int ocg = 0; ocg < 4; ocg++) {
        __syncthreads();
        if (wm == ocg) {
#pragma unroll
            for (int mt = 0; mt < 5; mt++)
#pragma unroll
                for (int nt = 0; nt < 8; nt++)
#pragma unroll
                    for (int j = 0; j < 4; j++) {
                        int row = mt * 16 + r4 + 8 * (j >> 1);
                        int col = wn * 64 + nt * 8 + 2 * q + (j & 1);
                        fE[row * 132 + col] =
                            to_tf32(acc[mt][nt][j] + fB[ocg * 80 + row]);
                    }
        }
        __syncthreads();

        if (ocg == 0) {
#pragma unroll
            for (int i = 0; i < 2; i++) {
                int item = tid + i * 256;
                if (item < 256) {
                    int n = item & 127, half = item >> 7;
                    float vv[32];
#pragma unroll
                    for (int o = 0; o < 32; o++)
                        vv[o] = fE[(half * 32 + o) * 132 + n];
                    float* dst = (half ? g_kt : g_qt) + ((size_t)b * NN + n0 + n) * CQK;
#pragma unroll
                    for (int og = 0; og < 4; og++) {
                        *(float4*)(dst + og * 8) =
                            make_float4(vv[og*8+0], vv[og*8+4], vv[og*8+1], vv[og*8+5]);
                        *(float4*)(dst + og * 8 + 4) =
                            make_float4(vv[og*8+2], vv[og*8+6], vv[og*8+3], vv[og*8+7]);
                    }
                } else {
                    int it = item - 256;
                    if (it < 128) {
                        int row = 64 + (it >> 3), gt = it & 7;
                        int c = row - 64;
                        const float* f = fE + row * 132 + gt * 16;
                        unsigned w[8];
#pragma unroll
                        for (int p = 0; p < 8; p++) w[p] = packbf(f[2*p], f[2*p+1]);
                        uint4* d = (uint4*)(g_v + ((size_t)b * CC + c) * NN + n0 + gt * 16);
                        d[0] = make_uint4(w[0], w[4], w[1], w[5]);
                        d[1] = make_uint4(w[2], w[6], w[3], w[7]);
                    }
                }
            }
        } else {
#pragma unroll
            for (int i = 0; i < 3; i++) {
                int item = tid + i * 256;
                if (item < 640) {
                    int row = item >> 3, gt = item & 7;
                    int c = ocg * 80 + row - 64;
                    const float* f = fE + row * 132 + gt * 16;
                    unsigned w[8];
#pragma unroll
                    for (int p = 0; p < 8; p++) w[p] = packbf(f[2*p], f[2*p+1]);
                    uint4* d = (uint4*)(g_v + ((size_t)b * CC + c) * NN + n0 + gt * 16);
                    d[0] = make_uint4(w[0], w[4], w[1], w[5]);
                    d[1] = make_uint4(w[2], w[6], w[3], w[7]);
                }
            }
        }
    }
}

// ===========================================================================
// 2) Flash attention, 64-row blocks, 2 CTAs/SM (4 warps/SMSP).
//    Warp tile: 16 n-rows (wr) x 128 c (wc half). Scores computed per warp
//    (duplicated across the c-pair); softmax warp-local; P packed to bf16
//    A-frags in regs. QK tf32, PV bf16 k16. One __syncthreads per step.
// ===========================================================================
__global__ __launch_bounds__(256, 2) void flash_kernel(const float* __restrict__ x,
                                                       float* __restrict__ out) {
    extern __shared__ float sm[];

    const int b   = blockIdx.y;
    const int n0  = blockIdx.x * 64;
    const int tid = threadIdx.x;
    const int wid = tid >> 5, lane = tid & 31;
    const int r4 = lane >> 2, q = lane & 3;
    const int wr = wid >> 1, wc = wid & 1;

    const unsigned sb  = smem_u32(sm);
    const unsigned sQ  = sb + OFF_Q * 4;
    const unsigned sK  = sb + OFF_K * 4;
    const unsigned sV  = sb + OFF_V * 4;

    const float* qg  = g_qt + ((size_t)b * NN + n0) * CQK;
    const float* kg0 = g_kt + (size_t)b * NN * CQK;
    const __nv_bfloat16* vg0 = g_v + (size_t)b * CC * NN;

    // ---- prologue: q tile (64x32) + first K/V tiles via cp.async
#pragma unroll
    for (int i = 0; i < 2; i++) {
        int idx = tid + i * 256;
        int row = idx >> 3, p = idx & 7;
        cp16(sQ + (unsigned)(row * 40 + p * 4) * 4, qg + (size_t)row * CQK + p * 4);
    }
    {
#pragma unroll
        for (int i = 0; i < 2; i++) {
            int idx = tid + i * 256;
            int row = idx >> 3, p = idx & 7;
            cp16(sK + (unsigned)(row * 40 + p * 4) * 4, kg0 + (size_t)row * CQK + p * 4);
        }
#pragma unroll
        for (int i = 0; i < 8; i++) {      // V: 256 c-rows x 32 words
            int idx = tid + i * 256;
            int row = idx >> 3, p = idx & 7;
            cp16(sV + (unsigned)(row * 40 + p * 4) * 4,
                 vg0 + (size_t)row * NN + p * 8);
        }
    }
    CP_COMMIT();
    CP_WAIT(0);
    __syncthreads();

    // q fragments: warp owns rows 16*wr..+15; fold LOG2E
    const int rowS = 16 * wr + r4;
    unsigned qf[4][4];
#pragma unroll
    for (int kk = 0; kk < 4; kk++) {
        unsigned ad = sQ + (unsigned)(rowS * 40 + kk * 8 + 2 * q) * 4;
        lds2(ad,              qf[kk][0], qf[kk][2]);
        lds2(ad + 8 * 40 * 4, qf[kk][1], qf[kk][3]);
    }
#pragma unroll
    for (int kk = 0; kk < 4; kk++)
#pragma unroll
        for (int j = 0; j < 4; j++)
            qf[kk][j] = __float_as_uint(to_tf32(LOG2E * __uint_as_float(qf[kk][j])));

    // out accumulator: 16 rows x 128 c -> 16 nt fragments
    float acc[16][4];
#pragma unroll
    for (int nt = 0; nt < 16; nt++)
#pragma unroll
        for (int j = 0; j < 4; j++) acc[nt][j] = 0.f;

    float mA = -1e30f, mB = -1e30f, lA = 0.f, lB = 0.f;

    const int STEPS = NN / 64;
    for (int s = 0; s < STEPS; s++) {
        if (s > 0) CP_WAIT(0);
        __syncthreads();   // K/V buf(s) visible; buf(s^1) reads finished

        if (s + 1 < STEPS) {
            const int m1 = (s + 1) * 64;
            const unsigned kd = sK + (unsigned)((s + 1) & 1) * (64 * 40 * 4);
            const float* kg = kg0 + (size_t)m1 * CQK;
#pragma unroll
            for (int i = 0; i < 2; i++) {
                int idx = tid + i * 256;
                int row = idx >> 3, p = idx & 7;
                cp16(kd + (unsigned)(row * 40 + p * 4) * 4, kg + (size_t)row * CQK + p * 4);
            }
            const unsigned vd = sV + (unsigned)((s + 1) & 1) * (256 * 40 * 4);
#pragma unroll
            for (int i = 0; i < 8; i++) {
                int idx = tid + i * 256;
                int row = idx >> 3, p = idx & 7;
                cp16(vd + (unsigned)(row * 40 + p * 4) * 4,
                     vg0 + (size_t)row * NN + m1 + p * 8);
            }
            CP_COMMIT();
        }

        // ---- scores (tf32): own 16 rows x 64 m (duplicated across c-pair)
        const unsigned kbuf = sK + (unsigned)(s & 1) * (64 * 40 * 4);
        float sacc[8][4];
#pragma unroll
        for (int nt = 0; nt < 8; nt++)
#pragma unroll
            for (int j = 0; j < 4; j++) sacc[nt][j] = 0.f;

#pragma unroll
        for (int kk = 0; kk < 4; kk++) {
            unsigned kb[8][2];
#pragma unroll
            for (int nt = 0; nt < 8; nt++)
                lds2(kbuf + (unsigned)((nt * 8 + r4) * 40 + kk * 8 + 2 * q) * 4,
                     kb[nt][0], kb[nt][1]);
#pragma unroll
            for (int nt = 0; nt < 8; nt++)
                mma8(sacc[nt], qf[kk][0], qf[kk][1], qf[kk][2], qf[kk][3],
                     kb[nt][0], kb[nt][1]);
        }

        // ---- online softmax (warp-local, base-2)
        float rmA = sacc[0][0], rmB = sacc[0][2];
#pragma unroll
        for (int nt = 0; nt < 8; nt++) {
            rmA = fmaxf(rmA, fmaxf(sacc[nt][0], sacc[nt][1]));
            rmB = fmaxf(rmB, fmaxf(sacc[nt][2], sacc[nt][3]));
        }
#pragma unroll
        for (int off = 1; off <= 2; off <<= 1) {
            rmA = fmaxf(rmA, __shfl_xor_sync(0xffffffffu, rmA, off));
            rmB = fmaxf(rmB, __shfl_xor_sync(0xffffffffu, rmB, off));
        }
        const float mnA = fmaxf(mA, rmA), mnB = fmaxf(mB, rmB);
        const float scA = ex2(mA - mnA),  scB = ex2(mB - mnB);
        mA = mnA; mB = mnB;

        float lsA = 0.f, lsB = 0.f;
#pragma unroll
        for (int nt = 0; nt < 8; nt++) {
            float p0 = ex2(sacc[nt][0] - mnA);
            float p1 = ex2(sacc[nt][1] - mnA);
            float p2 = ex2(sacc[nt][2] - mnB);
            float p3 = ex2(sacc[nt][3] - mnB);
            sacc[nt][0] = p0; sacc[nt][1] = p1; sacc[nt][2] = p2; sacc[nt][3] = p3;
            lsA += p0 + p1; lsB += p2 + p3;
        }
#pragma unroll
        for (int off = 1; off <= 2; off <<= 1) {
            lsA += __shfl_xor_sync(0xffffffffu, lsA, off);
            lsB += __shfl_xor_sync(0xffffffffu, lsB, off);
        }
        lA = lA * scA + lsA;
        lB = lB * scB + lsB;

        // ---- pack P to bf16 A-frags (sacc dies here)
        unsigned af[4][4];
#pragma unroll
        for (int g = 0; g < 4; g++) {
            af[g][0] = packbf(sacc[2*g][0],   sacc[2*g][1]);
            af[g][1] = packbf(sacc[2*g][2],   sacc[2*g][3]);
            af[g][2] = packbf(sacc[2*g+1][0], sacc[2*g+1][1]);
            af[g][3] = packbf(sacc[2*g+1][2], sacc[2*g+1][3]);
        }

        // ---- rescale acc (warp-local, skip when maxes unchanged)
        if (!__all_sync(0xffffffffu, (scA == 1.f) && (scB == 1.f))) {
#pragma unroll
            for (int nt = 0; nt < 16; nt++) {
                acc[nt][0] *= scA; acc[nt][1] *= scA;
                acc[nt][2] *= scB; acc[nt][3] *= scB;
            }
        }

        // ---- out MMA (bf16 k16): acc[16n x 128c] += P @ V^T over m=64
        const unsigned vbuf = sV + (unsigned)(s & 1) * (256 * 40 * 4);
#pragma unroll
        for (int g = 0; g < 4; g++) {
#pragma unroll
            for (int nt = 0; nt < 16; nt++) {
                unsigned b0, b1;
                lds2(vbuf + (unsigned)((wc * 128 + nt * 8 + r4) * 40 + g * 8 + 2 * q) * 4,
                     b0, b1);
                mma16bf(acc[nt], af[g][0], af[g][1], af[g][2], af[g][3], b0, b1);
            }
        }
    }

    // ---- normalize by l (warp-local)
    const float linvA = 1.f / lA, linvB = 1.f / lB;
#pragma unroll
    for (int nt = 0; nt < 16; nt++) {
        acc[nt][0] *= linvA; acc[nt][1] *= linvA;
        acc[nt][2] *= linvB; acc[nt][3] *= linvB;
    }

    // ---- epilogue: transpose 64n x 256c -> [c][n] via smem (reuse K+V), +x
    float* fT = sm + OFF_K;   // 256 x 68
    __syncthreads();
#pragma unroll
    for (int nt = 0; nt < 16; nt++)
#pragma unroll
        for (int j = 0; j < 4; j++) {
            int cl = wc * 128 + nt * 8 + 2 * q + (j & 1);
            int rn = rowS + 8 * (j >> 1);
            fT[cl * 68 + rn] = acc[nt][j];
        }
    __syncthreads();
    const float* xb = x   + (size_t)b * CC * NN + n0;
    float*       ob = out + (size_t)b * CC * NN + n0;
#pragma unroll
    for (int i = 0; i < 16; i++) {
        int idx = tid + i * 256;
        int cr = idx >> 4;
        int n4 = (idx & 15) * 4;
        float4 t = *(const float4*)&fT[cr * 68 + n4];
        const size_t go = (size_t)cr * NN + n4;
        float4 xv = *(const float4*)(xb + go);
        *(float4*)(ob + go) = make_float4(t.x + xv.x, t.y + xv.y,
                                          t.z + xv.z, t.w + xv.w);
    }
}

// ===========================================================================
extern "C" void kernel_launch(void* const* d_in, const int* in_sizes, int n_in,
                              void* d_out, int out_size) {
    const float* x  = (const float*)d_in[0];
    const float* Wq = (const float*)d_in[1];
    const float* bq = (const float*)d_in[2];
    const float* Wk = (const float*)d_in[3];
    const float* bk = (const float*)d_in[4];
    const float* Wv = (const float*)d_in[5];
    const float* bv = (const float*)d_in[6];
    float* out = (float*)d_out;

    const int pdyn = P_SMEM_FLOATS * 4;   // 130304 B
    cudaFuncSetAttribute(proj_fused_kernel,
                         cudaFuncAttributeMaxDynamicSharedMemorySize, pdyn);
    proj_fused_kernel<<<dim3(NN / 128, BB), 256, pdyn>>>(x, Wq, bq, Wk, bk, Wv, bv);

    const int fdyn = SMEM_FLOATS * 4;     // 112640 B
    cudaFuncSetAttribute(flash_kernel,
                         cudaFuncAttributeMaxDynamicSharedMemorySize, fdyn);
    flash_kernel<<<dim3(NN / 64, BB), 256, fdyn>>>(x, out);
}

// round 12
// speedup vs baseline: 2.0589x; 1.1582x over previous
#include <cuda_runtime.h>
#include <cuda_fp16.h>

#define BB  4
#define CC  256
#define CQK 32
#define NN  4096
#define LOG2E 1.4426950408889634f

// q/k: fp16 [b][n][c], word-pair-permuted per k16 chunk (8 words):
//   stored order [w0,w4,w1,w5,w2,w6,w3,w7] (word = 2 adjacent c).
//   q pre-scaled by log2(e).
// v: fp16 [b][c][m], same word-perm per 8-word (16-m) group.
__device__ __half g_qt[BB * NN * CQK];
__device__ __half g_kt[BB * NN * CQK];
__device__ __half g_v [(size_t)BB * CC * NN];

// ---- flash smem layout (32-bit word slots) — 64-row blocks
#define OFF_Q  0            // 64 x 24 (16 words/row + pad)
#define OFF_K  1536         // 2 x 64 x 24
#define OFF_V  4608         // 2 x 256 x 40
#define SMEM_FLOATS 25088   // 100352 B; epilogue fT 256x68 fp32 reuses OFF_K..

// ---- proj smem layout (floats)
#define P_OFF_SX 0          // 2 x 128 x 36
#define P_OFF_SW 9216       // 2 x 320 x 36
#define P_OFF_SB 32256      // 320
#define P_SMEM_FLOATS 32576 // 130304 bytes (epilogue 80x132 reuses P_OFF_SW)

// ===========================================================================
__device__ __forceinline__ unsigned smem_u32(const void* p) {
    unsigned a;
    asm("{ .reg .u64 t; cvta.to.shared.u64 t, %1; cvt.u32.u64 %0, t; }"
        : "=r"(a) : "l"(p));
    return a;
}
__device__ __forceinline__ float to_tf32(float x) {
    unsigned u;
    asm("cvt.rna.tf32.f32 %0, %1;" : "=r"(u) : "f"(x));
    return __uint_as_float(u);
}
__device__ __forceinline__ float ex2(float x) {
    float y;
    asm("ex2.approx.ftz.f32 %0, %1;" : "=f"(y) : "f"(x));
    return y;
}
// pack two fp32 -> f16x2 word (lo = first element)
__device__ __forceinline__ unsigned packh(float lo, float hi) {
    unsigned r;
    asm("cvt.rn.f16x2.f32 %0, %1, %2;" : "=r"(r) : "f"(hi), "f"(lo));
    return r;
}
__device__ __forceinline__ void cp16(unsigned dst, const void* src) {
    asm volatile("cp.async.cg.shared.global [%0], [%1], 16;" :: "r"(dst), "l"(src));
}
__device__ __forceinline__ void cp4(unsigned dst, const void* src) {
    asm volatile("cp.async.ca.shared.global [%0], [%1], 4;" :: "r"(dst), "l"(src));
}
#define CP_COMMIT()  asm volatile("cp.async.commit_group;")
#define CP_WAIT(n)   asm volatile("cp.async.wait_group %0;" :: "n"(n))

__device__ __forceinline__ void lds2(unsigned addr, unsigned& x, unsigned& y) {
    asm volatile("ld.shared.v2.b32 {%0, %1}, [%2];" : "=r"(x), "=r"(y) : "r"(addr));
}
__device__ __forceinline__ unsigned lds1(unsigned addr) {
    unsigned v;
    asm volatile("ld.shared.b32 %0, [%1];" : "=r"(v) : "r"(addr));
    return v;
}
__device__ __forceinline__ void mma8(float c[4],
                                     unsigned a0, unsigned a1, unsigned a2, unsigned a3,
                                     unsigned b0, unsigned b1) {
    asm volatile(
        "mma.sync.aligned.m16n8k8.row.col.f32.tf32.tf32.f32 "
        "{%0,%1,%2,%3}, {%4,%5,%6,%7}, {%8,%9}, {%0,%1,%2,%3};"
        : "+f"(c[0]), "+f"(c[1]), "+f"(c[2]), "+f"(c[3])
        : "r"(a0), "r"(a1), "r"(a2), "r"(a3), "r"(b0), "r"(b1));
}
__device__ __forceinline__ void mma16h(float c[4],
                                       unsigned a0, unsigned a1, unsigned a2, unsigned a3,
                                       unsigned b0, unsigned b1) {
    asm volatile(
        "mma.sync.aligned.m16n8k16.row.col.f32.f16.f16.f32 "
        "{%0,%1,%2,%3}, {%4,%5,%6,%7}, {%8,%9}, {%0,%1,%2,%3};"
        : "+f"(c[0]), "+f"(c[1]), "+f"(c[2]), "+f"(c[3])
        : "r"(a0), "r"(a1), "r"(a2), "r"(a3), "r"(b0), "r"(b1));
}

// ===========================================================================
// 1) Fused q+k+v projection via tensor cores (tf32 GEMM unchanged);
//    epilogue packs q/k/v to fp16 with word-perm; LOG2E folded into q.
// ===========================================================================
__global__ __launch_bounds__(256, 1) void proj_fused_kernel(
        const float* __restrict__ x,
        const float* __restrict__ Wq, const float* __restrict__ bq,
        const float* __restrict__ Wk, const float* __restrict__ bk,
        const float* __restrict__ Wv, const float* __restrict__ bv) {
    extern __shared__ float psm[];

    const int b   = blockIdx.y;
    const int n0  = blockIdx.x * 128;
    const int tid = threadIdx.x;
    const int wid = tid >> 5, lane = tid & 31;
    const int r4 = lane >> 2, q = lane & 3;
    const int wm = wid >> 1, wn = wid & 1;

    const unsigned sb4 = smem_u32(psm);
    const unsigned sX  = sb4 + P_OFF_SX * 4;
    const unsigned sW  = sb4 + P_OFF_SW * 4;
    float* fB = psm + P_OFF_SB;

    {
        int i = tid;
        if (i < 32) fB[i] = bq[i];
        else if (i < 64) fB[i] = bk[i - 32];
        else fB[i] = bv[i - 64];
        i = tid + 256;
        if (i < 320) fB[i] = bv[i - 64];
    }

    auto issue = [&](int ch) {
        const int buf = ch & 1;
        const unsigned wd = sW + (unsigned)buf * (320 * 36 * 4);
#pragma unroll
        for (int i = 0; i < 10; i++) {
            int idx = tid + i * 256;
            int row = idx >> 3, seg = idx & 7;
            int c = ch * 32 + seg * 4;
            const float* src = (row < 32) ? (Wq + row * 256 + c)
                             : (row < 64) ? (Wk + (row - 32) * 256 + c)
                                          : (Wv + (row - 64) * 256 + c);
            cp16(wd + (unsigned)(row * 36 + seg * 4) * 4, src);
        }
        const unsigned xd = sX + (unsigned)buf * (128 * 36 * 4);
#pragma unroll
        for (int i = 0; i < 16; i++) {
            int idx = tid + i * 256;
            int c = idx >> 7, n = idx & 127;
            cp4(xd + (unsigned)(n * 36 + c) * 4,
                x + ((size_t)b * CC + ch * 32 + c) * NN + n0 + n);
        }
        CP_COMMIT();
    };

    float acc[5][8][4];
#pragma unroll
    for (int mt = 0; mt < 5; mt++)
#pragma unroll
        for (int nt = 0; nt < 8; nt++)
#pragma unroll
            for (int j = 0; j < 4; j++) acc[mt][nt][j] = 0.f;

    issue(0);
    for (int ch = 0; ch < 8; ch++) {
        if (ch < 7) { issue(ch + 1); CP_WAIT(1); }
        else        { CP_WAIT(0); }
        __syncthreads();

        const int buf = ch & 1;
        const unsigned swb = sW + (unsigned)buf * (320 * 36 * 4);
        const unsigned sxb = sX + (unsigned)buf * (128 * 36 * 4);
#pragma unroll
        for (int kk = 0; kk < 4; kk++) {
            unsigned a[5][4];
#pragma unroll
            for (int mt = 0; mt < 5; mt++) {
                unsigned base = swb + (unsigned)((wm * 80 + mt * 16 + r4) * 36 + kk * 8 + q) * 4;
                a[mt][0] = lds1(base);
                a[mt][1] = lds1(base + 8 * 36 * 4);
                a[mt][2] = lds1(base + 16);
                a[mt][3] = lds1(base + 8 * 36 * 4 + 16);
            }
            unsigned bb[8][2];
#pragma unroll
            for (int nt = 0; nt < 8; nt++) {
                unsigned nb = sxb + (unsigned)((wn * 64 + nt * 8 + r4) * 36 + kk * 8 + q) * 4;
                bb[nt][0] = lds1(nb);
                bb[nt][1] = lds1(nb + 16);
            }
#pragma unroll
            for (int mt = 0; mt < 5; mt++)
#pragma unroll
                for (int nt = 0; nt < 8; nt++)
                    mma8(acc[mt][nt], a[mt][0], a[mt][1], a[mt][2], a[mt][3],
                         bb[nt][0], bb[nt][1]);
        }
        __syncthreads();
    }

    float* fE = psm + P_OFF_SW;   // 80 x 132
#pragma unroll 1
    for (int ocg = 0; ocg < 4; ocg++) {
        __syncthreads();
        if (wm == ocg) {
#pragma unroll
            for (int mt = 0; mt < 5; mt++)
#pragma unroll
                for (int nt = 0; nt < 8; nt++)
#pragma unroll
                    for (int j = 0; j < 4; j++) {
                        int row = mt * 16 + r4 + 8 * (j >> 1);
                        int col = wn * 64 + nt * 8 + 2 * q + (j & 1);
                        fE[row * 132 + col] = acc[mt][nt][j] + fB[ocg * 80 + row];
                    }
        }
        __syncthreads();

        if (ocg == 0) {
            // rows 0..31: q, rows 32..63: k -> fp16 [n][c-wordperm];
            // rows 64..79: v c=0..15 fp16
#pragma unroll
            for (int i = 0; i < 2; i++) {
                int item = tid + i * 256;
                if (item < 256) {
                    int n = item & 127, half = item >> 7;
                    const float sc = half ? 1.0f : LOG2E;
                    float vv[32];
#pragma unroll
                    for (int o = 0; o < 32; o++)
                        vv[o] = fE[(half * 32 + o) * 132 + n] * sc;
                    unsigned w[16];
#pragma unroll
                    for (int j = 0; j < 16; j++) w[j] = packh(vv[2*j], vv[2*j+1]);
                    __half* hdst = (half ? g_kt : g_qt) + ((size_t)b * NN + n0 + n) * CQK;
                    uint4* d = (uint4*)hdst;
                    d[0] = make_uint4(w[0],  w[4],  w[1],  w[5]);
                    d[1] = make_uint4(w[2],  w[6],  w[3],  w[7]);
                    d[2] = make_uint4(w[8],  w[12], w[9],  w[13]);
                    d[3] = make_uint4(w[10], w[14], w[11], w[15]);
                } else {
                    int it = item - 256;
                    if (it < 128) {
                        int row = 64 + (it >> 3), gt = it & 7;
                        int c = row - 64;
                        const float* f = fE + row * 132 + gt * 16;
                        unsigned w[8];
#pragma unroll
                        for (int p = 0; p < 8; p++) w[p] = packh(f[2*p], f[2*p+1]);
                        uint4* d = (uint4*)(g_v + ((size_t)b * CC + c) * NN + n0 + gt * 16);
                        d[0] = make_uint4(w[0], w[4], w[1], w[5]);
                        d[1] = make_uint4(w[2], w[6], w[3], w[7]);
                    }
                }
            }
        } else {
#pragma unroll
            for (int i = 0; i < 3; i++) {
                int item = tid + i * 256;
                if (item < 640) {
                    int row = item >> 3, gt = item & 7;
                    int c = ocg * 80 + row - 64;
                    const float* f = fE + row * 132 + gt * 16;
                    unsigned w[8];
#pragma unroll
                    for (int p = 0; p < 8; p++) w[p] = packh(f[2*p], f[2*p+1]);
                    uint4* d = (uint4*)(g_v + ((size_t)b * CC + c) * NN + n0 + gt * 16);
                    d[0] = make_uint4(w[0], w[4], w[1], w[5]);
                    d[1] = make_uint4(w[2], w[6], w[3], w[7]);
                }
            }
        }
    }
}

// ===========================================================================
// 2) Flash attention, 64-row blocks, 2 CTAs/SM. All-fp16 operands:
//    QK fp16 m16n8k16 (was tf32 k8), PV fp16 m16n8k16. Warp tile 16n x 128c.
//    One __syncthreads per step.
// ===========================================================================
__global__ __launch_bounds__(256, 2) void flash_kernel(const float* __restrict__ x,
                                                       float* __restrict__ out) {
    extern __shared__ float sm[];

    const int b   = blockIdx.y;
    const int n0  = blockIdx.x * 64;
    const int tid = threadIdx.x;
    const int wid = tid >> 5, lane = tid & 31;
    const int r4 = lane >> 2, q = lane & 3;
    const int wr = wid >> 1, wc = wid & 1;

    const unsigned sb  = smem_u32(sm);
    const unsigned sQ  = sb + OFF_Q * 4;
    const unsigned sK  = sb + OFF_K * 4;
    const unsigned sV  = sb + OFF_V * 4;

    const __half* qg  = g_qt + ((size_t)b * NN + n0) * CQK;
    const __half* kg0 = g_kt + (size_t)b * NN * CQK;
    const __half* vg0 = g_v  + (size_t)b * CC * NN;

    // ---- prologue: q tile (64x32 fp16) + first K/V tiles via cp.async
    cp16(sQ + (unsigned)((tid >> 2) * 24 + (tid & 3) * 4) * 4,
         qg + (size_t)(tid >> 2) * CQK + (tid & 3) * 8);
    cp16(sK + (unsigned)((tid >> 2) * 24 + (tid & 3) * 4) * 4,
         kg0 + (size_t)(tid >> 2) * CQK + (tid & 3) * 8);
#pragma unroll
    for (int i = 0; i < 8; i++) {      // V: 256 c-rows x 32 words
        int idx = tid + i * 256;
        int row = idx >> 3, p = idx & 7;
        cp16(sV + (unsigned)(row * 40 + p * 4) * 4,
             vg0 + (size_t)row * NN + p * 8);
    }
    CP_COMMIT();
    CP_WAIT(0);
    __syncthreads();

    // q fragments: warp owns rows 16*wr..+15 (LOG2E pre-folded)
    const int rowS = 16 * wr + r4;
    unsigned qf[2][4];
#pragma unroll
    for (int kk = 0; kk < 2; kk++) {
        lds2(sQ + (unsigned)(rowS * 24 + kk * 8 + 2 * q) * 4,
             qf[kk][0], qf[kk][2]);
        lds2(sQ + (unsigned)((rowS + 8) * 24 + kk * 8 + 2 * q) * 4,
             qf[kk][1], qf[kk][3]);
    }

    // out accumulator: 16 rows x 128 c -> 16 nt fragments
    float acc[16][4];
#pragma unroll
    for (int nt = 0; nt < 16; nt++)
#pragma unroll
        for (int j = 0; j < 4; j++) acc[nt][j] = 0.f;

    float mA = -1e30f, mB = -1e30f, lA = 0.f, lB = 0.f;

    const int STEPS = NN / 64;
    for (int s = 0; s < STEPS; s++) {
        if (s > 0) CP_WAIT(0);
        __syncthreads();   // K/V buf(s) visible; buf(s^1) reads finished

        if (s + 1 < STEPS) {
            const int m1 = (s + 1) * 64;
            const unsigned kd = sK + (unsigned)((s + 1) & 1) * (64 * 24 * 4);
            cp16(kd + (unsigned)((tid >> 2) * 24 + (tid & 3) * 4) * 4,
                 kg0 + (size_t)(m1 + (tid >> 2)) * CQK + (tid & 3) * 8);
            const unsigned vd = sV + (unsigned)((s + 1) & 1) * (256 * 40 * 4);
#pragma unroll
            for (int i = 0; i < 8; i++) {
                int idx = tid + i * 256;
                int row = idx >> 3, p = idx & 7;
                cp16(vd + (unsigned)(row * 40 + p * 4) * 4,
                     vg0 + (size_t)row * NN + m1 + p * 8);
            }
            CP_COMMIT();
        }

        // ---- scores (fp16 k16): own 16 rows x 64 m (duplicated across c-pair)
        const unsigned kbuf = sK + (unsigned)(s & 1) * (64 * 24 * 4);
        float sacc[8][4];
#pragma unroll
        for (int nt = 0; nt < 8; nt++)
#pragma unroll
            for (int j = 0; j < 4; j++) sacc[nt][j] = 0.f;

#pragma unroll
        for (int kk = 0; kk < 2; kk++) {
#pragma unroll
            for (int nt = 0; nt < 8; nt++) {
                unsigned b0, b1;
                lds2(kbuf + (unsigned)((nt * 8 + r4) * 24 + kk * 8 + 2 * q) * 4,
                     b0, b1);
                mma16h(sacc[nt], qf[kk][0], qf[kk][1], qf[kk][2], qf[kk][3],
                       b0, b1);
            }
        }

        // ---- online softmax (warp-local, base-2)
        float rmA = sacc[0][0], rmB = sacc[0][2];
#pragma unroll
        for (int nt = 0; nt < 8; nt++) {
            rmA = fmaxf(rmA, fmaxf(sacc[nt][0], sacc[nt][1]));
            rmB = fmaxf(rmB, fmaxf(sacc[nt][2], sacc[nt][3]));
        }
#pragma unroll
        for (int off = 1; off <= 2; off <<= 1) {
            rmA = fmaxf(rmA, __shfl_xor_sync(0xffffffffu, rmA, off));
            rmB = fmaxf(rmB, __shfl_xor_sync(0xffffffffu, rmB, off));
        }
        const float mnA = fmaxf(mA, rmA), mnB = fmaxf(mB, rmB);
        const float scA = ex2(mA - mnA),  scB = ex2(mB - mnB);
        mA = mnA; mB = mnB;

        float lsA = 0.f, lsB = 0.f;
#pragma unroll
        for (int nt = 0; nt < 8; nt++) {
            float p0 = ex2(sacc[nt][0] - mnA);
            float p1 = ex2(sacc[nt][1] - mnA);
            float p2 = ex2(sacc[nt][2] - mnB);
            float p3 = ex2(sacc[nt][3] - mnB);
            sacc[nt][0] = p0; sacc[nt][1] = p1;
            sacc[nt][2] = p2; sacc[nt][3] = p3;
            lsA += p0 + p1; lsB += p2 + p3;
        }
#pragma unroll
        for (int off = 1; off <= 2; off <<= 1) {
            lsA += __shfl_xor_sync(0xffffffffu, lsA, off);
            lsB += __shfl_xor_sync(0xffffffffu, lsB, off);
        }
        lA = lA * scA + lsA;
        lB = lB * scB + lsB;

        // ---- pack P to fp16 A-frags (sacc dies here)
        unsigned af[4][4];
#pragma unroll
        for (int g = 0; g < 4; g++) {
            af[g][0] = packh(sacc[2*g][0],   sacc[2*g][1]);
            af[g][1] = packh(sacc[2*g][2],   sacc[2*g][3]);
            af[g][2] = packh(sacc[2*g+1][0], sacc[2*g+1][1]);
            af[g][3] = packh(sacc[2*g+1][2], sacc[2*g+1][3]);
        }

        // ---- rescale acc (warp-local, skip when maxes unchanged)
        if (!__all_sync(0xffffffffu, (scA == 1.f) && (scB == 1.f))) {
#pragma unroll
            for (int nt = 0; nt < 16; nt++) {
                acc[nt][0] *= scA; acc[nt][1] *= scA;
                acc[nt][2] *= scB; acc[nt][3] *= scB;
            }
        }

        // ---- out MMA (fp16 k16): acc[16n x 128c] += P @ V^T over m=64
        const unsigned vbuf = sV + (unsigned)(s & 1) * (256 * 40 * 4);
#pragma unroll
        for (int g = 0; g < 4; g++) {
#pragma unroll
            for (int nt = 0; nt < 16; nt++) {
                unsigned b0, b1;
                lds2(vbuf + (unsigned)((wc * 128 + nt * 8 + r4) * 40 + g * 8 + 2 * q) * 4,
                     b0, b1);
                mma16h(acc[nt], af[g][0], af[g][1], af[g][2], af[g][3], b0, b1);
            }
        }
    }

    // ---- normalize by l (warp-local)
    const float linvA = 1.f / lA, linvB = 1.f / lB;
#pragma unroll
    for (int nt = 0; nt < 16; nt++) {
        acc[nt][0] *= linvA; acc[nt][1] *= linvA;
        acc[nt][2] *= linvB; acc[nt][3] *= linvB;
    }

    // ---- epilogue: transpose 64n x 256c -> [c][n] via smem (reuse K+V), +x
    float* fT = sm + OFF_K;   // 256 x 68
    __syncthreads();
#pragma unroll
    for (int nt = 0; nt < 16; nt++)
#pragma unroll
        for (int j = 0; j < 4; j++) {
            int cl = wc * 128 + nt * 8 + 2 * q + (j & 1);
            int rn = rowS + 8 * (j >> 1);
            fT[cl * 68 + rn] = acc[nt][j];
        }
    __syncthreads();
    const float* xb = x   + (size_t)b * CC * NN + n0;
    float*       ob = out + (size_t)b * CC * NN + n0;
#pragma unroll
    for (int i = 0; i < 16; i++) {
        int idx = tid + i * 256;
        int cr = idx >> 4;
        int n4 = (idx & 15) * 4;
        float4 t = *(const float4*)&fT[cr * 68 + n4];
        const size_t go = (size_t)cr * NN + n4;
        float4 xv = *(const float4*)(xb + go);
        *(float4*)(ob + go) = make_float4(t.x + xv.x, t.y + xv.y,
                                          t.z + xv.z, t.w + xv.w);
    }
}

// ===========================================================================
extern "C" void kernel_launch(void* const* d_in, const int* in_sizes, int n_in,
                              void* d_out, int out_size) {
    const float* x  = (const float*)d_in[0];
    const float* Wq = (const float*)d_in[1];
    const float* bq = (const float*)d_in[2];
    const float* Wk = (const float*)d_in[3];
    const float* bk = (const float*)d_in[4];
    const float* Wv = (const float*)d_in[5];
    const float* bv = (const float*)d_in[6];
    float* out = (float*)d_out;

    const int pdyn = P_SMEM_FLOATS * 4;   // 130304 B
    cudaFuncSetAttribute(proj_fused_kernel,
                         cudaFuncAttributeMaxDynamicSharedMemorySize, pdyn);
    proj_fused_kernel<<<dim3(NN / 128, BB), 256, pdyn>>>(x, Wq, bq, Wk, bk, Wv, bv);

    const int fdyn = SMEM_FLOATS * 4;     // 100352 B
    cudaFuncSetAttribute(flash_kernel,
                         cudaFuncAttributeMaxDynamicSharedMemorySize, fdyn);
    flash_kernel<<<dim3(NN / 64, BB), 256, fdyn>>>(x, out);
}